// round 2
// baseline (speedup 1.0000x reference)
#include <cuda_runtime.h>
#include <cstdint>

#define NBATCH 4
#define NP     4096
#define DIM    256
#define NC     5
#define NROWS  (NBATCH * NP)

#define INV_T  14.285714285714286f            /* 1/0.07 */
#define CQ     20.60992915555662f             /* log2(e)/0.07 */
#define LN2F   0.6931471805599453f

// -------- persistent scratch (no allocations allowed) --------
__device__ float g_m [NROWS];    // per-row running max of (logit * CQ) over non-same-class cols
__device__ float g_s [NROWS];    // per-row sum 2^(q - m)
__device__ float g_mn[NROWS];    // per-row min of raw logit over non-same-class cols
__device__ float g_smallest[NBATCH][NC];
__device__ int   g_counts  [NBATCH][NC];
__device__ int   g_chunkpref[NBATCH][32][NC];

// -------- packed f32x2 helpers (Blackwell FFMA2 path) --------
__device__ __forceinline__ unsigned long long f2pack(float lo, float hi) {
    unsigned long long r;
    asm("mov.b64 %0, {%1, %2};" : "=l"(r) : "f"(lo), "f"(hi));
    return r;
}
__device__ __forceinline__ void f2unpack(unsigned long long v, float& lo, float& hi) {
    asm("mov.b64 {%0, %1}, %2;" : "=f"(lo), "=f"(hi) : "l"(v));
}
__device__ __forceinline__ unsigned long long ffma2(unsigned long long a,
                                                    unsigned long long b,
                                                    unsigned long long c) {
    unsigned long long d;
    asm("fma.rn.f32x2 %0, %1, %2, %3;" : "=l"(d) : "l"(a), "l"(b), "l"(c));
    return d;
}

// ============================================================================
// Kernel 1: fused GEMM + masked online-softmax/min row reductions.
// Block: 256 threads, BM=64 rows (A resident in SMEM), BN=128 col tile streamed.
// Thread tile: 4 rows x 8 cols as 4x4 f32x2 accumulators.
// ============================================================================
__global__ __launch_bounds__(256, 2)
void nce_gemm(const float* __restrict__ src, const float* __restrict__ tgt,
              const int* __restrict__ cls)
{
    extern __shared__ float smp[];
    float* AsF = smp;                 // [256][64]  = 64 KB, A^T resident
    float* BsB = smp + 256 * 64;      // [2][16][128] = 16 KB, B double buffer

    const int   tid = threadIdx.x;
    const int   tx  = tid & 15;       // col group (8 cols)
    const int   ty  = tid >> 4;       // row group (4 rows)
    const int   bx  = blockIdx.x;     // row tile 0..63
    const int   b   = blockIdx.y;     // batch
    const int   R0  = b * NP + bx * 64;
    const float NEGINF = __int_as_float(0xff800000);
    const float POSINF = __int_as_float(0x7f800000);

    // ---- load A tile (64 x 256) into SMEM, k-major transposed ----
    const float* Ag = src + (size_t)R0 * DIM;
#pragma unroll
    for (int i = 0; i < 16; i++) {
        int idx = tid + 256 * i;
        int r = idx >> 6, q = idx & 63;
        float4 v = *(const float4*)(Ag + r * DIM + q * 4);
        AsF[(q * 4 + 0) * 64 + r] = v.x;
        AsF[(q * 4 + 1) * 64 + r] = v.y;
        AsF[(q * 4 + 2) * 64 + r] = v.z;
        AsF[(q * 4 + 3) * 64 + r] = v.w;
    }

    int rcls[4];
#pragma unroll
    for (int ii = 0; ii < 4; ii++) rcls[ii] = cls[R0 + ty * 4 + ii];

    float m_[4], s_[4], mn_[4];
#pragma unroll
    for (int ii = 0; ii < 4; ii++) { m_[ii] = NEGINF; s_[ii] = 0.f; mn_[ii] = POSINF; }

    // B-tile loader mapping: 128 rows x 16 k = 512 float4, 2 per thread
    const int l0r = tid >> 2, lq = tid & 3;
    const int l1r = l0r + 64;

    for (int ct = 0; ct < 32; ct++) {
        const int    C0 = b * NP + ct * 128;
        const float* Bg = tgt + (size_t)C0 * DIM;

        unsigned long long acc[4][4];
#pragma unroll
        for (int ii = 0; ii < 4; ii++)
#pragma unroll
            for (int j = 0; j < 4; j++) acc[ii][j] = 0ULL;

        // preload B chunk 0 into buffer 0
        {
            float4 v0 = *(const float4*)(Bg + l0r * DIM + lq * 4);
            float4 v1 = *(const float4*)(Bg + l1r * DIM + lq * 4);
            float* B0 = BsB;
            B0[(lq * 4 + 0) * 128 + l0r] = v0.x;
            B0[(lq * 4 + 1) * 128 + l0r] = v0.y;
            B0[(lq * 4 + 2) * 128 + l0r] = v0.z;
            B0[(lq * 4 + 3) * 128 + l0r] = v0.w;
            B0[(lq * 4 + 0) * 128 + l1r] = v1.x;
            B0[(lq * 4 + 1) * 128 + l1r] = v1.y;
            B0[(lq * 4 + 2) * 128 + l1r] = v1.z;
            B0[(lq * 4 + 3) * 128 + l1r] = v1.w;
        }
        __syncthreads();

#pragma unroll 1
        for (int kk = 0; kk < 16; kk++) {
            const int cur = kk & 1;
            float4 p0, p1;
            if (kk < 15) {
                const float* Bg2 = Bg + (kk + 1) * 16;
                p0 = *(const float4*)(Bg2 + l0r * DIM + lq * 4);
                p1 = *(const float4*)(Bg2 + l1r * DIM + lq * 4);
            }
            const float* Bcur = BsB + cur * (16 * 128);
            const float* Acur = AsF + kk * (16 * 64);
#pragma unroll
            for (int k = 0; k < 16; k++) {
                float4 av  = *(const float4*)(Acur + k * 64 + ty * 4);
                float4 bv0 = *(const float4*)(Bcur + k * 128 + tx * 8);
                float4 bv1 = *(const float4*)(Bcur + k * 128 + tx * 8 + 4);
                unsigned long long b20 = f2pack(bv0.x, bv0.y);
                unsigned long long b21 = f2pack(bv0.z, bv0.w);
                unsigned long long b22 = f2pack(bv1.x, bv1.y);
                unsigned long long b23 = f2pack(bv1.z, bv1.w);
                float a4[4] = {av.x, av.y, av.z, av.w};
#pragma unroll
                for (int ii = 0; ii < 4; ii++) {
                    unsigned long long a2 = f2pack(a4[ii], a4[ii]);
                    acc[ii][0] = ffma2(a2, b20, acc[ii][0]);
                    acc[ii][1] = ffma2(a2, b21, acc[ii][1]);
                    acc[ii][2] = ffma2(a2, b22, acc[ii][2]);
                    acc[ii][3] = ffma2(a2, b23, acc[ii][3]);
                }
            }
            if (kk < 15) {
                float* Bn = BsB + ((cur ^ 1) * (16 * 128));
                Bn[(lq * 4 + 0) * 128 + l0r] = p0.x;
                Bn[(lq * 4 + 1) * 128 + l0r] = p0.y;
                Bn[(lq * 4 + 2) * 128 + l0r] = p0.z;
                Bn[(lq * 4 + 3) * 128 + l0r] = p0.w;
                Bn[(lq * 4 + 0) * 128 + l1r] = p1.x;
                Bn[(lq * 4 + 1) * 128 + l1r] = p1.y;
                Bn[(lq * 4 + 2) * 128 + l1r] = p1.z;
                Bn[(lq * 4 + 3) * 128 + l1r] = p1.w;
            }
            __syncthreads();
        }

        // ---- masked online update for this 128-col tile ----
        int ccls[8];
#pragma unroll
        for (int jj = 0; jj < 8; jj++) ccls[jj] = cls[C0 + tx * 8 + jj];

#pragma unroll
        for (int ii = 0; ii < 4; ii++) {
            float l[8];
            f2unpack(acc[ii][0], l[0], l[1]);
            f2unpack(acc[ii][1], l[2], l[3]);
            f2unpack(acc[ii][2], l[4], l[5]);
            f2unpack(acc[ii][3], l[6], l[7]);
            float q[8];
            float tmax = NEGINF;
#pragma unroll
            for (int jj = 0; jj < 8; jj++) {
                bool ok = (ccls[jj] != rcls[ii]);
                q[jj] = ok ? l[jj] * CQ : NEGINF;
                if (ok) mn_[ii] = fminf(mn_[ii], l[jj]);
                tmax = fmaxf(tmax, q[jj]);
            }
            if (tmax != NEGINF) {
                float nm  = fmaxf(m_[ii], tmax);
                float add = 0.f;
#pragma unroll
                for (int jj = 0; jj < 8; jj++) add += exp2f(q[jj] - nm);
                s_[ii] = s_[ii] * exp2f(m_[ii] - nm) + add;
                m_[ii] = nm;
            }
        }
    }

    // ---- cross-tx (16-way) merge of per-row states, alias SMEM ----
    float* redm = smp;             // [16][64]
    float* reds = smp + 1024;
    float* redn = smp + 2048;
#pragma unroll
    for (int ii = 0; ii < 4; ii++) {
        int r = ty * 4 + ii;
        redm[tx * 64 + r] = m_[ii];
        reds[tx * 64 + r] = s_[ii];
        redn[tx * 64 + r] = mn_[ii];
    }
    __syncthreads();
    if (tid < 64) {
        const int r = tid;
        float M = NEGINF, S = 0.f, MN = POSINF;
#pragma unroll
        for (int t = 0; t < 16; t++) M = fmaxf(M, redm[t * 64 + r]);
        if (M != NEGINF) {
#pragma unroll
            for (int t = 0; t < 16; t++) S += reds[t * 64 + r] * exp2f(redm[t * 64 + r] - M);
        }
#pragma unroll
        for (int t = 0; t < 16; t++) MN = fminf(MN, redn[t * 64 + r]);
        g_m [R0 + r] = M;
        g_s [R0 + r] = S;
        g_mn[R0 + r] = MN;
    }
}

// ============================================================================
// Kernel 2: per-batch class counts, class-min -> smallest, chunk prefix table.
// grid = NBATCH, 256 threads.
// ============================================================================
__device__ __forceinline__ unsigned fkey(float x) {
    unsigned u = __float_as_uint(x);
    return (u & 0x80000000u) ? ~u : (u | 0x80000000u);
}
__device__ __forceinline__ float funkey(unsigned k) {
    unsigned u = (k & 0x80000000u) ? (k & 0x7FFFFFFFu) : ~k;
    return __uint_as_float(u);
}

__global__ void nce_classred(const int* __restrict__ cls)
{
    const int b = blockIdx.x, tid = threadIdx.x;
    __shared__ int      scls[NP];
    __shared__ int      scnt[NC];
    __shared__ unsigned smink[NC];
    __shared__ int      hist[32][NC];

    for (int i = tid; i < NP; i += 256) scls[i] = cls[b * NP + i];
    if (tid < NC) { scnt[tid] = 0; smink[tid] = 0xFF800000u; /* key(+inf) */ }
    __syncthreads();

    int   lc[NC] = {0, 0, 0, 0, 0};
    float lm[NC];
#pragma unroll
    for (int c = 0; c < NC; c++) lm[c] = __int_as_float(0x7f800000);
    for (int i = tid; i < NP; i += 256) {
        int c = scls[i];
        lc[c]++;
        lm[c] = fminf(lm[c], g_mn[b * NP + i]);
    }
#pragma unroll
    for (int c = 0; c < NC; c++) {
        if (lc[c]) atomicAdd(&scnt[c], lc[c]);
        atomicMin(&smink[c], fkey(lm[c]));
    }
    __syncthreads();

    if (tid < NC) {
        int c = tid;
        g_counts[b][c] = scnt[c];
        float cm = funkey(smink[c]);
        g_smallest[b][c] = fminf(cm, -10.0f) * INV_T;
    }
    if (tid < 32 * NC) {
        int ch = tid / NC, c = tid % NC;
        int h = 0;
        for (int i = 0; i < 128; i++) h += (scls[ch * 128 + i] == c);
        hist[ch][c] = h;
    }
    __syncthreads();
    if (tid < NC) {
        int c = tid;
        int run = 0;
        for (int c2 = 0; c2 < c; c2++) run += scnt[c2];
        for (int ch = 0; ch < 32; ch++) {
            g_chunkpref[b][ch][c] = run;
            run += hist[ch][c];
        }
    }
}

// ============================================================================
// Kernel 3: final 3-way logsumexp + stable class-sorted scatter.
// grid = (32, NBATCH), 128 threads (one row each).
// ============================================================================
__global__ void nce_final(const float* __restrict__ src, const float* __restrict__ tgt,
                          const int* __restrict__ cls, float* __restrict__ out)
{
    const int ch = blockIdx.x, b = blockIdx.y, tid = threadIdx.x;
    const int row = b * NP + ch * 128 + tid;
    const float NEGINF = __int_as_float(0xff800000);

    __shared__ int scls[128];
    const int c = cls[row];
    scls[tid] = c;
    __syncthreads();

    int lr = 0;
    for (int j = 0; j < tid; j++) lr += (scls[j] == c);
    const int opos = b * NP + g_chunkpref[b][ch][c] + lr;

    // positive logit: diagonal dot
    const float4* s4 = (const float4*)(src + (size_t)row * DIM);
    const float4* t4 = (const float4*)(tgt + (size_t)row * DIM);
    float p0 = 0.f, p1 = 0.f, p2 = 0.f, p3 = 0.f;
#pragma unroll
    for (int d = 0; d < 64; d++) {
        float4 a = s4[d], v = t4[d];
        p0 += a.x * v.x; p1 += a.y * v.y; p2 += a.z * v.z; p3 += a.w * v.w;
    }
    const float pos_n = (p0 + p1 + p2 + p3) * INV_T;

    const float M = g_m[row], S = g_s[row];
    const float lneg = (S > 0.f) ? (M * LN2F + logf(S)) : NEGINF;

    const int   npad = g_counts[b][c] - 1;
    const float pad  = (npad > 0) ? (logf((float)npad) + g_smallest[b][c]) : NEGINF;

    const float Mx  = fmaxf(pos_n, fmaxf(lneg, pad));
    const float sum = expf(pos_n - Mx) + expf(lneg - Mx) + expf(pad - Mx);
    out[opos] = Mx + logf(sum) - pos_n;
}

// ============================================================================
extern "C" void kernel_launch(void* const* d_in, const int* in_sizes, int n_in,
                              void* d_out, int out_size)
{
    const float* src = (const float*)d_in[0];
    const float* tgt = (const float*)d_in[1];
    const int*   cls = (const int*)d_in[2];
    float*       out = (float*)d_out;

    const int smem_bytes = (256 * 64 + 2 * 16 * 128) * (int)sizeof(float); // 80 KB
    cudaFuncSetAttribute(nce_gemm, cudaFuncAttributeMaxDynamicSharedMemorySize, smem_bytes);

    nce_gemm<<<dim3(64, NBATCH), 256, smem_bytes>>>(src, tgt, cls);
    nce_classred<<<NBATCH, 256>>>(cls);
    nce_final<<<dim3(32, NBATCH), 128>>>(src, tgt, cls, out);
}

// round 3
// speedup vs baseline: 1.0025x; 1.0025x over previous
#include <cuda_runtime.h>
#include <cstdint>

#define NBATCH 4
#define NP     4096
#define DIM    256
#define NC     5
#define NROWS  (NBATCH * NP)

#define INV_T  14.285714285714286f            /* 1/0.07 */
#define CQ     20.60992915555662f             /* log2(e)/0.07 */
#define LN2F   0.6931471805599453f

// -------- persistent scratch (no allocations allowed) --------
__device__ float g_m [NROWS];    // per-row running max of (logit * CQ) over non-same-class cols
__device__ float g_s [NROWS];    // per-row sum 2^(q - m)
__device__ float g_mn[NROWS];    // per-row min of raw logit over non-same-class cols
__device__ float g_smallest[NBATCH][NC];
__device__ int   g_counts  [NBATCH][NC];
__device__ int   g_chunkpref[NBATCH][32][NC];

// -------- packed f32x2 helpers (Blackwell FFMA2 path) --------
__device__ __forceinline__ unsigned long long f2pack(float lo, float hi) {
    unsigned long long r;
    asm("mov.b64 %0, {%1, %2};" : "=l"(r) : "f"(lo), "f"(hi));
    return r;
}
__device__ __forceinline__ void f2unpack(unsigned long long v, float& lo, float& hi) {
    asm("mov.b64 {%0, %1}, %2;" : "=f"(lo), "=f"(hi) : "l"(v));
}
__device__ __forceinline__ unsigned long long ffma2(unsigned long long a,
                                                    unsigned long long b,
                                                    unsigned long long c) {
    unsigned long long d;
    asm("fma.rn.f32x2 %0, %1, %2, %3;" : "=l"(d) : "l"(a), "l"(b), "l"(c));
    return d;
}

// ============================================================================
// Kernel 1: fused GEMM + masked online-softmax/min row reductions.
// Block: 256 threads, BM=64 rows (A resident in SMEM), BN=128 col tile streamed.
// Thread tile: 4 rows x 8 cols as 4x4 f32x2 accumulators.
// ============================================================================
__global__ __launch_bounds__(256, 2)
void nce_gemm(const float* __restrict__ src, const float* __restrict__ tgt,
              const int* __restrict__ cls)
{
    extern __shared__ float smp[];
    float* AsF = smp;                 // [256][64]  = 64 KB, A^T resident
    float* BsB = smp + 256 * 64;      // [2][16][128] = 16 KB, B double buffer

    const int   tid = threadIdx.x;
    const int   tx  = tid & 15;       // col group (8 cols)
    const int   ty  = tid >> 4;       // row group (4 rows)
    const int   bx  = blockIdx.x;     // row tile 0..63
    const int   b   = blockIdx.y;     // batch
    const int   R0  = b * NP + bx * 64;
    const float NEGINF = __int_as_float(0xff800000);
    const float POSINF = __int_as_float(0x7f800000);

    // ---- load A tile (64 x 256) into SMEM, k-major transposed ----
    const float* Ag = src + (size_t)R0 * DIM;
#pragma unroll
    for (int i = 0; i < 16; i++) {
        int idx = tid + 256 * i;
        int r = idx >> 6, q = idx & 63;
        float4 v = *(const float4*)(Ag + r * DIM + q * 4);
        AsF[(q * 4 + 0) * 64 + r] = v.x;
        AsF[(q * 4 + 1) * 64 + r] = v.y;
        AsF[(q * 4 + 2) * 64 + r] = v.z;
        AsF[(q * 4 + 3) * 64 + r] = v.w;
    }

    int rcls[4];
#pragma unroll
    for (int ii = 0; ii < 4; ii++) rcls[ii] = cls[R0 + ty * 4 + ii];

    float m_[4], s_[4], mn_[4];
#pragma unroll
    for (int ii = 0; ii < 4; ii++) { m_[ii] = NEGINF; s_[ii] = 0.f; mn_[ii] = POSINF; }

    // B-tile loader mapping: 128 rows x 16 k = 512 float4, 2 per thread
    const int l0r = tid >> 2, lq = tid & 3;
    const int l1r = l0r + 64;

    for (int ct = 0; ct < 32; ct++) {
        const int    C0 = b * NP + ct * 128;
        const float* Bg = tgt + (size_t)C0 * DIM;

        unsigned long long acc[4][4];
#pragma unroll
        for (int ii = 0; ii < 4; ii++)
#pragma unroll
            for (int j = 0; j < 4; j++) acc[ii][j] = 0ULL;

        // preload B chunk 0 into buffer 0
        {
            float4 v0 = *(const float4*)(Bg + l0r * DIM + lq * 4);
            float4 v1 = *(const float4*)(Bg + l1r * DIM + lq * 4);
            float* B0 = BsB;
            B0[(lq * 4 + 0) * 128 + l0r] = v0.x;
            B0[(lq * 4 + 1) * 128 + l0r] = v0.y;
            B0[(lq * 4 + 2) * 128 + l0r] = v0.z;
            B0[(lq * 4 + 3) * 128 + l0r] = v0.w;
            B0[(lq * 4 + 0) * 128 + l1r] = v1.x;
            B0[(lq * 4 + 1) * 128 + l1r] = v1.y;
            B0[(lq * 4 + 2) * 128 + l1r] = v1.z;
            B0[(lq * 4 + 3) * 128 + l1r] = v1.w;
        }
        __syncthreads();

#pragma unroll 1
        for (int kk = 0; kk < 16; kk++) {
            const int cur = kk & 1;
            float4 p0, p1;
            if (kk < 15) {
                const float* Bg2 = Bg + (kk + 1) * 16;
                p0 = *(const float4*)(Bg2 + l0r * DIM + lq * 4);
                p1 = *(const float4*)(Bg2 + l1r * DIM + lq * 4);
            }
            const float* Bcur = BsB + cur * (16 * 128);
            const float* Acur = AsF + kk * (16 * 64);
#pragma unroll
            for (int k = 0; k < 16; k++) {
                float4 av  = *(const float4*)(Acur + k * 64 + ty * 4);
                float4 bv0 = *(const float4*)(Bcur + k * 128 + tx * 8);
                float4 bv1 = *(const float4*)(Bcur + k * 128 + tx * 8 + 4);
                unsigned long long b20 = f2pack(bv0.x, bv0.y);
                unsigned long long b21 = f2pack(bv0.z, bv0.w);
                unsigned long long b22 = f2pack(bv1.x, bv1.y);
                unsigned long long b23 = f2pack(bv1.z, bv1.w);
                float a4[4] = {av.x, av.y, av.z, av.w};
#pragma unroll
                for (int ii = 0; ii < 4; ii++) {
                    unsigned long long a2 = f2pack(a4[ii], a4[ii]);
                    acc[ii][0] = ffma2(a2, b20, acc[ii][0]);
                    acc[ii][1] = ffma2(a2, b21, acc[ii][1]);
                    acc[ii][2] = ffma2(a2, b22, acc[ii][2]);
                    acc[ii][3] = ffma2(a2, b23, acc[ii][3]);
                }
            }
            if (kk < 15) {
                float* Bn = BsB + ((cur ^ 1) * (16 * 128));
                Bn[(lq * 4 + 0) * 128 + l0r] = p0.x;
                Bn[(lq * 4 + 1) * 128 + l0r] = p0.y;
                Bn[(lq * 4 + 2) * 128 + l0r] = p0.z;
                Bn[(lq * 4 + 3) * 128 + l0r] = p0.w;
                Bn[(lq * 4 + 0) * 128 + l1r] = p1.x;
                Bn[(lq * 4 + 1) * 128 + l1r] = p1.y;
                Bn[(lq * 4 + 2) * 128 + l1r] = p1.z;
                Bn[(lq * 4 + 3) * 128 + l1r] = p1.w;
            }
            __syncthreads();
        }

        // ---- masked online update for this 128-col tile ----
        int ccls[8];
#pragma unroll
        for (int jj = 0; jj < 8; jj++) ccls[jj] = cls[C0 + tx * 8 + jj];

#pragma unroll
        for (int ii = 0; ii < 4; ii++) {
            float l[8];
            f2unpack(acc[ii][0], l[0], l[1]);
            f2unpack(acc[ii][1], l[2], l[3]);
            f2unpack(acc[ii][2], l[4], l[5]);
            f2unpack(acc[ii][3], l[6], l[7]);
            float q[8];
            float tmax = NEGINF;
#pragma unroll
            for (int jj = 0; jj < 8; jj++) {
                bool ok = (ccls[jj] != rcls[ii]);
                q[jj] = ok ? l[jj] * CQ : NEGINF;
                if (ok) mn_[ii] = fminf(mn_[ii], l[jj]);
                tmax = fmaxf(tmax, q[jj]);
            }
            if (tmax != NEGINF) {
                float nm  = fmaxf(m_[ii], tmax);
                float add = 0.f;
#pragma unroll
                for (int jj = 0; jj < 8; jj++) add += exp2f(q[jj] - nm);
                s_[ii] = s_[ii] * exp2f(m_[ii] - nm) + add;
                m_[ii] = nm;
            }
        }
    }

    // ---- cross-tx (16-way) merge of per-row states, alias SMEM ----
    float* redm = smp;             // [16][64]
    float* reds = smp + 1024;
    float* redn = smp + 2048;
#pragma unroll
    for (int ii = 0; ii < 4; ii++) {
        int r = ty * 4 + ii;
        redm[tx * 64 + r] = m_[ii];
        reds[tx * 64 + r] = s_[ii];
        redn[tx * 64 + r] = mn_[ii];
    }
    __syncthreads();
    if (tid < 64) {
        const int r = tid;
        float M = NEGINF, S = 0.f, MN = POSINF;
#pragma unroll
        for (int t = 0; t < 16; t++) M = fmaxf(M, redm[t * 64 + r]);
        if (M != NEGINF) {
#pragma unroll
            for (int t = 0; t < 16; t++) S += reds[t * 64 + r] * exp2f(redm[t * 64 + r] - M);
        }
#pragma unroll
        for (int t = 0; t < 16; t++) MN = fminf(MN, redn[t * 64 + r]);
        g_m [R0 + r] = M;
        g_s [R0 + r] = S;
        g_mn[R0 + r] = MN;
    }
}

// ============================================================================
// Kernel 2: per-batch class counts, class-min -> smallest, chunk prefix table.
// grid = NBATCH, 256 threads.
// ============================================================================
__device__ __forceinline__ unsigned fkey(float x) {
    unsigned u = __float_as_uint(x);
    return (u & 0x80000000u) ? ~u : (u | 0x80000000u);
}
__device__ __forceinline__ float funkey(unsigned k) {
    unsigned u = (k & 0x80000000u) ? (k & 0x7FFFFFFFu) : ~k;
    return __uint_as_float(u);
}

__global__ void nce_classred(const int* __restrict__ cls)
{
    const int b = blockIdx.x, tid = threadIdx.x;
    __shared__ int      scls[NP];
    __shared__ int      scnt[NC];
    __shared__ unsigned smink[NC];
    __shared__ int      hist[32][NC];

    for (int i = tid; i < NP; i += 256) scls[i] = cls[b * NP + i];
    if (tid < NC) { scnt[tid] = 0; smink[tid] = 0xFF800000u; /* key(+inf) */ }
    __syncthreads();

    int   lc[NC] = {0, 0, 0, 0, 0};
    float lm[NC];
#pragma unroll
    for (int c = 0; c < NC; c++) lm[c] = __int_as_float(0x7f800000);
    for (int i = tid; i < NP; i += 256) {
        int c = scls[i];
        lc[c]++;
        lm[c] = fminf(lm[c], g_mn[b * NP + i]);
    }
#pragma unroll
    for (int c = 0; c < NC; c++) {
        if (lc[c]) atomicAdd(&scnt[c], lc[c]);
        atomicMin(&smink[c], fkey(lm[c]));
    }
    __syncthreads();

    if (tid < NC) {
        int c = tid;
        g_counts[b][c] = scnt[c];
        float cm = funkey(smink[c]);
        g_smallest[b][c] = fminf(cm, -10.0f) * INV_T;
    }
    if (tid < 32 * NC) {
        int ch = tid / NC, c = tid % NC;
        int h = 0;
        for (int i = 0; i < 128; i++) h += (scls[ch * 128 + i] == c);
        hist[ch][c] = h;
    }
    __syncthreads();
    if (tid < NC) {
        int c = tid;
        int run = 0;
        for (int c2 = 0; c2 < c; c2++) run += scnt[c2];
        for (int ch = 0; ch < 32; ch++) {
            g_chunkpref[b][ch][c] = run;
            run += hist[ch][c];
        }
    }
}

// ============================================================================
// Kernel 3: final 3-way logsumexp + stable class-sorted scatter.
// grid = (32, NBATCH), 128 threads (one row each).
// ============================================================================
__global__ void nce_final(const float* __restrict__ src, const float* __restrict__ tgt,
                          const int* __restrict__ cls, float* __restrict__ out)
{
    const int ch = blockIdx.x, b = blockIdx.y, tid = threadIdx.x;
    const int row = b * NP + ch * 128 + tid;
    const float NEGINF = __int_as_float(0xff800000);

    __shared__ int scls[128];
    const int c = cls[row];
    scls[tid] = c;
    __syncthreads();

    int lr = 0;
    for (int j = 0; j < tid; j++) lr += (scls[j] == c);
    const int opos = b * NP + g_chunkpref[b][ch][c] + lr;

    // positive logit: diagonal dot
    const float4* s4 = (const float4*)(src + (size_t)row * DIM);
    const float4* t4 = (const float4*)(tgt + (size_t)row * DIM);
    float p0 = 0.f, p1 = 0.f, p2 = 0.f, p3 = 0.f;
#pragma unroll
    for (int d = 0; d < 64; d++) {
        float4 a = s4[d], v = t4[d];
        p0 += a.x * v.x; p1 += a.y * v.y; p2 += a.z * v.z; p3 += a.w * v.w;
    }
    const float pos_n = (p0 + p1 + p2 + p3) * INV_T;

    const float M = g_m[row], S = g_s[row];
    const float lneg = (S > 0.f) ? (M * LN2F + logf(S)) : NEGINF;

    const int   npad = g_counts[b][c] - 1;
    const float pad  = (npad > 0) ? (logf((float)npad) + g_smallest[b][c]) : NEGINF;

    const float Mx  = fmaxf(pos_n, fmaxf(lneg, pad));
    const float sum = expf(pos_n - Mx) + expf(lneg - Mx) + expf(pad - Mx);
    out[opos] = Mx + logf(sum) - pos_n;
}

// ============================================================================
extern "C" void kernel_launch(void* const* d_in, const int* in_sizes, int n_in,
                              void* d_out, int out_size)
{
    const float* src = (const float*)d_in[0];
    const float* tgt = (const float*)d_in[1];
    const int*   cls = (const int*)d_in[2];
    float*       out = (float*)d_out;

    const int smem_bytes = (256 * 64 + 2 * 16 * 128) * (int)sizeof(float); // 80 KB
    cudaFuncSetAttribute(nce_gemm, cudaFuncAttributeMaxDynamicSharedMemorySize, smem_bytes);

    nce_gemm<<<dim3(64, NBATCH), 256, smem_bytes>>>(src, tgt, cls);
    nce_classred<<<NBATCH, 256>>>(cls);
    nce_final<<<dim3(32, NBATCH), 128>>>(src, tgt, cls, out);
}

// round 6
// speedup vs baseline: 3.9195x; 3.9099x over previous
#include <cuda_runtime.h>
#include <cuda_bf16.h>
#include <cstdint>

#define NBATCH 4
#define NP     4096
#define DIM    256
#define NC     5
#define NROWS  (NBATCH * NP)

#define INV_T  14.285714285714286f            /* 1/0.07 */
#define CQ     20.60992915555662f             /* log2(e)/0.07 */
#define LN2F   0.6931471805599453f

/* ---- SMEM layout (bytes) ---- */
#define SM_A     0          /* Ah 65536 + Al 65536 (128 rows x 512B, swizzled) */
#define SM_B     131072     /* 2 stages x (Bh 16384 + Bl 16384) */
#define SM_CLS   196608     /* 4096 ints */
#define SMEM_BYTES 212992

/* ---- persistent scratch (no allocations allowed) ---- */
__device__ uint32_t g_Ah[NROWS * DIM / 2];   /* src hi split, bf16x2-packed */
__device__ uint32_t g_Al[NROWS * DIM / 2];
__device__ uint32_t g_Bh[NROWS * DIM / 2];   /* tgt hi split */
__device__ uint32_t g_Bl[NROWS * DIM / 2];
__device__ float g_m [NROWS];
__device__ float g_s [NROWS];
__device__ float g_mn[NROWS];
__device__ float g_smallest[NBATCH][NC];
__device__ int   g_counts  [NBATCH][NC];
__device__ int   g_chunkpref[NBATCH][32][NC];

/* ================= helpers ================= */
__device__ __forceinline__ uint32_t smem_u32(const void* p) {
    uint32_t a;
    asm("{ .reg .u64 t; cvta.to.shared.u64 t, %1; cvt.u32.u64 %0, t; }" : "=r"(a) : "l"(p));
    return a;
}
__device__ __forceinline__ float ex2f(float x) {
    float y; asm("ex2.approx.ftz.f32 %0, %1;" : "=f"(y) : "f"(x)); return y;
}
__device__ __forceinline__ void cp16(uint32_t dst, const void* src) {
    asm volatile("cp.async.cg.shared.global [%0], [%1], 16;" :: "r"(dst), "l"(src));
}
#define CP_COMMIT() asm volatile("cp.async.commit_group;" ::: "memory")
#define CP_WAIT1()  asm volatile("cp.async.wait_group 1;" ::: "memory")
#define CP_WAIT0()  asm volatile("cp.async.wait_group 0;" ::: "memory")

__device__ __forceinline__ void ldsm4(uint32_t (&r)[4], uint32_t addr) {
    asm volatile("ldmatrix.sync.aligned.m8n8.x4.shared.b16 {%0,%1,%2,%3}, [%4];"
                 : "=r"(r[0]), "=r"(r[1]), "=r"(r[2]), "=r"(r[3]) : "r"(addr));
}
__device__ __forceinline__ void mma16816(float (&d)[4], const uint32_t* a, const uint32_t* b) {
    asm volatile("mma.sync.aligned.m16n8k16.row.col.f32.bf16.bf16.f32 "
                 "{%0,%1,%2,%3}, {%4,%5,%6,%7}, {%8,%9}, {%0,%1,%2,%3};"
                 : "+f"(d[0]), "+f"(d[1]), "+f"(d[2]), "+f"(d[3])
                 : "r"(a[0]), "r"(a[1]), "r"(a[2]), "r"(a[3]), "r"(b[0]), "r"(b[1]));
}
__device__ __forceinline__ uint32_t pk2(float a, float b) {
    __nv_bfloat16 ha = __float2bfloat16(a), hb = __float2bfloat16(b);
    return (uint32_t)__bfloat16_as_ushort(ha) | ((uint32_t)__bfloat16_as_ushort(hb) << 16);
}

/* ================= Kernel 0: fp32 -> bf16 hi/lo splits ================= */
__global__ __launch_bounds__(256)
void cvt_split(const float* __restrict__ in, int which)
{
    int i = blockIdx.x * 256 + threadIdx.x;        /* float4 index */
    float4 v = ((const float4*)in)[i];
    __nv_bfloat16 hx = __float2bfloat16(v.x), hy = __float2bfloat16(v.y);
    __nv_bfloat16 hz = __float2bfloat16(v.z), hw = __float2bfloat16(v.w);
    uint2 h = make_uint2(
        (uint32_t)__bfloat16_as_ushort(hx) | ((uint32_t)__bfloat16_as_ushort(hy) << 16),
        (uint32_t)__bfloat16_as_ushort(hz) | ((uint32_t)__bfloat16_as_ushort(hw) << 16));
    uint2 l = make_uint2(pk2(v.x - __bfloat162float(hx), v.y - __bfloat162float(hy)),
                         pk2(v.z - __bfloat162float(hz), v.w - __bfloat162float(hw)));
    if (which) { ((uint2*)g_Bh)[i] = h; ((uint2*)g_Bl)[i] = l; }
    else       { ((uint2*)g_Ah)[i] = h; ((uint2*)g_Al)[i] = l; }
}

/* ================= Kernel 1: bf16-split mma.sync GEMM + fused masked softmax ===
   grid (32 M-tiles, 4 batches), 256 threads = 8 warps as 4(M) x 2(N).
   Warp tile 32x64. A (128x256 hi+lo) resident in SMEM; B streamed in
   64-k chunks, double-buffered cp.async.                                       */
__global__ __launch_bounds__(256, 1)
void nce_gemm_mma(const int* __restrict__ cls)
{
    extern __shared__ __align__(1024) char smem[];
    const uint32_t sb = smem_u32(smem);
    const int tid = threadIdx.x, lane = tid & 31, w = tid >> 5;
    const int wm = w >> 1, wn = w & 1;
    const int b = blockIdx.y, mtB = blockIdx.x;
    const int R0 = b * NP + mtB * 128;
    const float NEGINF = __int_as_float(0xff800000);
    const float POSINF = __int_as_float(0x7f800000);

    int* scls = (int*)(smem + SM_CLS);

    /* ---- preload A (both splits): 8192 16B lines, swizzled chunk^row ---- */
    {
#pragma unroll
        for (int q = 0; q < 32; q++) {
            int line = tid + q * 256;
            int split = line >> 12;
            int li = line & 4095;
            int mrow = li >> 5, c = li & 31;
            uint32_t dst = sb + SM_A + (uint32_t)split * 65536u
                         + (uint32_t)mrow * 512u + (uint32_t)((c ^ (mrow & 7)) << 4);
            const uint32_t* g = split ? g_Al : g_Ah;
            cp16(dst, g + (size_t)(R0 + mrow) * 128 + c * 4);
        }
    }

    /* ---- B chunk loader: chunk i = (ct=i>>2, kc=i&3), 64 k-values ---- */
    auto loadB = [&](int i, int stage) {
        const int ct = i >> 2, kc = i & 3;
        const size_t rb = (size_t)(b * NP + ct * 128) * 128 + (size_t)kc * 32;
#pragma unroll
        for (int sp = 0; sp < 2; sp++) {
            const uint32_t* g = sp ? g_Bl : g_Bh;
            uint32_t dbase = sb + SM_B + (uint32_t)stage * 32768u + (uint32_t)sp * 16384u;
#pragma unroll
            for (int ii = 0; ii < 4; ii++) {
                int q = tid * 4 + ii;               /* 0..1023 */
                int n = q >> 3, c = q & 7;
                uint32_t dst = dbase + (uint32_t)n * 128u + (uint32_t)((c ^ (n & 7)) << 4);
                cp16(dst, g + rb + (size_t)n * 128 + c * 4);
            }
        }
    };
    loadB(0, 0); CP_COMMIT();
    loadB(1, 1); CP_COMMIT();

    /* ---- class table ---- */
#pragma unroll
    for (int q = 0; q < 4; q++)
        ((int4*)scls)[tid + q * 256] = ((const int4*)(cls + b * NP))[tid + q * 256];
    __syncthreads();

    /* per-lane row classes: slot j=(mt*2+h) -> row wm*32 + mt*16 + h*8 + lane/4 */
    int rcls[4];
#pragma unroll
    for (int j = 0; j < 4; j++)
        rcls[j] = scls[mtB * 128 + wm * 32 + (j >> 1) * 16 + (j & 1) * 8 + (lane >> 2)];

    float m_[4], s_[4], mn_[4];
#pragma unroll
    for (int j = 0; j < 4; j++) { m_[j] = NEGINF; s_[j] = 0.f; mn_[j] = POSINF; }

    /* lane address components (ldmatrix group = lane>>3) */
    const int la7 = lane & 7;
    const uint32_t aRowOff = (uint32_t)(wm * 32 + ((lane >> 3) & 1) * 8 + la7) * 512u;
    const int aKg = lane >> 4;                 /* A: groups 0,1 -> k0 ; 2,3 -> k8 */
    const uint32_t bRowOff = (uint32_t)(wn * 64 + ((lane >> 4) & 1) * 8 + la7) * 128u;
    const int bKg = (lane >> 3) & 1;           /* B: groups 0,2 -> k0 ; 1,3 -> k8 */

    float acc[2][8][4];

#pragma unroll 1
    for (int i = 0; i < 128; i++) {
        if (i < 127) { CP_WAIT1(); } else { CP_WAIT0(); }
        __syncthreads();
        const int kc = i & 3, stage = i & 1, ct = i >> 2;
        if (kc == 0) {
#pragma unroll
            for (int mt = 0; mt < 2; mt++)
#pragma unroll
                for (int nt = 0; nt < 8; nt++)
#pragma unroll
                    for (int j = 0; j < 4; j++) acc[mt][nt][j] = 0.f;
        }
        const uint32_t Bst = sb + SM_B + (uint32_t)stage * 32768u;

#pragma unroll
        for (int ks = 0; ks < 4; ks++) {
            uint32_t ah[2][4], al[2][4];
#pragma unroll
            for (int mt = 0; mt < 2; mt++) {
                uint32_t ca = (uint32_t)((kc * 8 + ks * 2 + aKg) ^ la7) << 4;
                uint32_t base = sb + SM_A + aRowOff + (uint32_t)mt * 8192u + ca;
                ldsm4(ah[mt], base);
                ldsm4(al[mt], base + 65536u);
            }
            uint32_t bh[4][4], bl[4][4];
#pragma unroll
            for (int p = 0; p < 4; p++) {
                uint32_t cb = (uint32_t)((ks * 2 + bKg) ^ la7) << 4;
                uint32_t base = Bst + bRowOff + (uint32_t)p * 2048u + cb;
                ldsm4(bh[p], base);
                ldsm4(bl[p], base + 16384u);
            }
#pragma unroll
            for (int mt = 0; mt < 2; mt++)
#pragma unroll
                for (int p = 0; p < 4; p++)
#pragma unroll
                    for (int hh = 0; hh < 2; hh++) {
                        int nt = p * 2 + hh;
                        mma16816(acc[mt][nt], ah[mt], &bh[p][hh * 2]);
                        mma16816(acc[mt][nt], ah[mt], &bl[p][hh * 2]);
                        mma16816(acc[mt][nt], al[mt], &bh[p][hh * 2]);
                    }
        }

        if (kc == 3) {
            /* ---- masked online update for this 128-col tile ---- */
            const int colbase = ct * 128 + wn * 64 + (lane & 3) * 2;
            int ccls[16];
#pragma unroll
            for (int nt = 0; nt < 8; nt++) {
                ccls[nt * 2]     = scls[colbase + nt * 8];
                ccls[nt * 2 + 1] = scls[colbase + nt * 8 + 1];
            }
#pragma unroll
            for (int j = 0; j < 4; j++) {
                const int mt = j >> 1, hh = j & 1;
                float tmax = NEGINF;
#pragma unroll
                for (int nt = 0; nt < 8; nt++) {
                    float l0 = acc[mt][nt][hh * 2], l1 = acc[mt][nt][hh * 2 + 1];
                    if (ccls[nt * 2] != rcls[j])     { mn_[j] = fminf(mn_[j], l0); tmax = fmaxf(tmax, l0); }
                    if (ccls[nt * 2 + 1] != rcls[j]) { mn_[j] = fminf(mn_[j], l1); tmax = fmaxf(tmax, l1); }
                }
                if (tmax != NEGINF) {
                    float nm = fmaxf(m_[j], tmax * CQ);
                    float a0 = 0.f, a1 = 0.f;
#pragma unroll
                    for (int nt = 0; nt < 8; nt++) {
                        float l0 = acc[mt][nt][hh * 2], l1 = acc[mt][nt][hh * 2 + 1];
                        a0 += ex2f((ccls[nt * 2] != rcls[j])     ? l0 * CQ - nm : NEGINF);
                        a1 += ex2f((ccls[nt * 2 + 1] != rcls[j]) ? l1 * CQ - nm : NEGINF);
                    }
                    s_[j] = s_[j] * ex2f(m_[j] - nm) + a0 + a1;
                    m_[j] = nm;
                }
            }
        }
        __syncthreads();
        if (i + 2 < 128) { loadB(i + 2, stage); CP_COMMIT(); }
    }

    /* ---- merge across the 4 lanes sharing each row (lane bits 0,1) ---- */
#pragma unroll
    for (int j = 0; j < 4; j++) {
#pragma unroll
        for (int d = 1; d <= 2; d <<= 1) {
            float om = __shfl_xor_sync(0xFFFFFFFFu, m_[j], d);
            float os = __shfl_xor_sync(0xFFFFFFFFu, s_[j], d);
            float on = __shfl_xor_sync(0xFFFFFFFFu, mn_[j], d);
            float nm = fmaxf(m_[j], om);
            float t0 = (m_[j] == NEGINF) ? 0.f : s_[j] * ex2f(m_[j] - nm);
            float t1 = (om == NEGINF) ? 0.f : os * ex2f(om - nm);
            s_[j] = t0 + t1; m_[j] = nm; mn_[j] = fminf(mn_[j], on);
        }
    }

    /* ---- cross-warp (wn 0/1) merge via SMEM (reuse B region) ---- */
    float* mgM = (float*)(smem + SM_B);        /* [2][128] */
    float* mgS = mgM + 256;
    float* mgN = mgS + 256;
    if ((lane & 3) == 0) {
#pragma unroll
        for (int j = 0; j < 4; j++) {
            int row = wm * 32 + (j >> 1) * 16 + (j & 1) * 8 + (lane >> 2);
            mgM[wn * 128 + row] = m_[j];
            mgS[wn * 128 + row] = s_[j];
            mgN[wn * 128 + row] = mn_[j];
        }
    }
    __syncthreads();
    if (tid < 128) {
        float m0 = mgM[tid], m1 = mgM[128 + tid];
        float nm = fmaxf(m0, m1);
        float S = ((m0 == NEGINF) ? 0.f : mgS[tid] * ex2f(m0 - nm))
                + ((m1 == NEGINF) ? 0.f : mgS[128 + tid] * ex2f(m1 - nm));
        g_m [R0 + tid] = nm;
        g_s [R0 + tid] = S;
        g_mn[R0 + tid] = fminf(mgN[tid], mgN[128 + tid]);
    }
}

/* ================= Kernel 2: per-batch class reductions ================= */
__device__ __forceinline__ unsigned fkey(float x) {
    unsigned u = __float_as_uint(x);
    return (u & 0x80000000u) ? ~u : (u | 0x80000000u);
}
__device__ __forceinline__ float funkey(unsigned k) {
    unsigned u = (k & 0x80000000u) ? (k & 0x7FFFFFFFu) : ~k;
    return __uint_as_float(u);
}

__global__ void nce_classred(const int* __restrict__ cls)
{
    const int b = blockIdx.x, tid = threadIdx.x;
    __shared__ int      scls[NP];
    __shared__ int      scnt[NC];
    __shared__ unsigned smink[NC];
    __shared__ int      hist[32][NC];

    for (int i = tid; i < NP; i += 256) scls[i] = cls[b * NP + i];
    if (tid < NC) { scnt[tid] = 0; smink[tid] = 0xFF800000u; }
    __syncthreads();

    int   lc[NC] = {0, 0, 0, 0, 0};
    float lm[NC];
#pragma unroll
    for (int c = 0; c < NC; c++) lm[c] = __int_as_float(0x7f800000);
    for (int i = tid; i < NP; i += 256) {
        int c = scls[i];
        lc[c]++;
        lm[c] = fminf(lm[c], g_mn[b * NP + i]);
    }
#pragma unroll
    for (int c = 0; c < NC; c++) {
        if (lc[c]) atomicAdd(&scnt[c], lc[c]);
        atomicMin(&smink[c], fkey(lm[c]));
    }
    __syncthreads();

    if (tid < NC) {
        g_counts[b][tid] = scnt[tid];
        g_smallest[b][tid] = fminf(funkey(smink[tid]), -10.0f) * INV_T;
    }
    if (tid < 32 * NC) {
        int ch = tid / NC, c = tid % NC;
        int h = 0;
        for (int i = 0; i < 128; i++) h += (scls[ch * 128 + i] == c);
        hist[ch][c] = h;
    }
    __syncthreads();
    if (tid < NC) {
        int c = tid, run = 0;
        for (int c2 = 0; c2 < c; c2++) run += scnt[c2];
        for (int ch = 0; ch < 32; ch++) { g_chunkpref[b][ch][c] = run; run += hist[ch][c]; }
    }
}

/* ================= Kernel 3: final 3-way LSE + stable class-sorted scatter ===== */
__global__ void nce_final(const float* __restrict__ src, const float* __restrict__ tgt,
                          const int* __restrict__ cls, float* __restrict__ out)
{
    const int ch = blockIdx.x, b = blockIdx.y, tid = threadIdx.x;
    const int row = b * NP + ch * 128 + tid;
    const float NEGINF = __int_as_float(0xff800000);

    __shared__ int scls[128];
    const int c = cls[row];
    scls[tid] = c;
    __syncthreads();

    int lr = 0;
    for (int j = 0; j < tid; j++) lr += (scls[j] == c);
    const int opos = b * NP + g_chunkpref[b][ch][c] + lr;

    const float4* s4 = (const float4*)(src + (size_t)row * DIM);
    const float4* t4 = (const float4*)(tgt + (size_t)row * DIM);
    float p0 = 0.f, p1 = 0.f, p2 = 0.f, p3 = 0.f;
#pragma unroll
    for (int d = 0; d < 64; d++) {
        float4 a = s4[d], v = t4[d];
        p0 += a.x * v.x; p1 += a.y * v.y; p2 += a.z * v.z; p3 += a.w * v.w;
    }
    const float pos_n = (p0 + p1 + p2 + p3) * INV_T;

    const float M = g_m[row], S = g_s[row];
    const float lneg = (S > 0.f) ? (M * LN2F + logf(S)) : NEGINF;

    const int   npad = g_counts[b][c] - 1;
    const float pad  = (npad > 0) ? (logf((float)npad) + g_smallest[b][c]) : NEGINF;

    const float Mx  = fmaxf(pos_n, fmaxf(lneg, pad));
    const float sum = expf(pos_n - Mx) + expf(lneg - Mx) + expf(pad - Mx);
    out[opos] = Mx + logf(sum) - pos_n;
}

/* ============================================================================ */
extern "C" void kernel_launch(void* const* d_in, const int* in_sizes, int n_in,
                              void* d_out, int out_size)
{
    const float* src = (const float*)d_in[0];
    const float* tgt = (const float*)d_in[1];
    const int*   cls = (const int*)d_in[2];
    float*       out = (float*)d_out;

    cudaFuncSetAttribute(nce_gemm_mma, cudaFuncAttributeMaxDynamicSharedMemorySize, SMEM_BYTES);

    cvt_split<<<NROWS * DIM / 4 / 256, 256>>>(src, 0);
    cvt_split<<<NROWS * DIM / 4 / 256, 256>>>(tgt, 1);
    nce_gemm_mma<<<dim3(32, NBATCH), 256, SMEM_BYTES>>>(cls);
    nce_classred<<<NBATCH, 256>>>(cls);
    nce_final<<<dim3(32, NBATCH), 128>>>(src, tgt, cls, out);
}

// round 7
// speedup vs baseline: 5.6953x; 1.4531x over previous
#include <cuda_runtime.h>
#include <cuda_fp16.h>
#include <cstdint>

#define NBATCH 4
#define NP     4096
#define DIM    256
#define NC     5
#define NROWS  (NBATCH * NP)

#define INV_T  14.285714285714286f            /* 1/0.07 */
#define CQ     20.60992915555662f             /* log2(e)/0.07 */
#define LN2F   0.6931471805599453f

/* ---- SMEM layout (bytes) ---- */
#define SM_A     0          /* Ah: 128 rows x 512B, swizzled (64 KB) */
#define SM_B     65536      /* 3 stages x (Bh 16384 + Bl 16384) = 96 KB */
#define SM_CLS   163840     /* 4096 ints */
#define SMEM_BYTES 180224

/* ---- persistent scratch (no allocations allowed) ---- */
__device__ uint32_t g_Ah[NROWS * DIM / 2];   /* src hi (fp16x2-packed) */
__device__ uint32_t g_Bh[NROWS * DIM / 2];   /* tgt hi */
__device__ uint32_t g_Bl[NROWS * DIM / 2];   /* tgt lo */
__device__ float g_m [NROWS];
__device__ float g_s [NROWS];
__device__ float g_mn[NROWS];
__device__ int      g_hist [NBATCH][32][NC];
__device__ unsigned g_chmin[NBATCH][32][NC];
__device__ float g_smallest[NBATCH][NC];
__device__ int   g_counts  [NBATCH][NC];
__device__ int   g_chunkpref[NBATCH][32][NC];

/* ================= helpers ================= */
__device__ __forceinline__ uint32_t smem_u32(const void* p) {
    uint32_t a;
    asm("{ .reg .u64 t; cvta.to.shared.u64 t, %1; cvt.u32.u64 %0, t; }" : "=r"(a) : "l"(p));
    return a;
}
__device__ __forceinline__ float ex2f(float x) {
    float y; asm("ex2.approx.ftz.f32 %0, %1;" : "=f"(y) : "f"(x)); return y;
}
__device__ __forceinline__ void cp16(uint32_t dst, const void* src) {
    asm volatile("cp.async.cg.shared.global [%0], [%1], 16;" :: "r"(dst), "l"(src));
}
#define CP_COMMIT() asm volatile("cp.async.commit_group;" ::: "memory")
#define CP_WAIT1()  asm volatile("cp.async.wait_group 1;" ::: "memory")
#define CP_WAIT0()  asm volatile("cp.async.wait_group 0;" ::: "memory")

__device__ __forceinline__ void ldsm4(uint32_t (&r)[4], uint32_t addr) {
    asm volatile("ldmatrix.sync.aligned.m8n8.x4.shared.b16 {%0,%1,%2,%3}, [%4];"
                 : "=r"(r[0]), "=r"(r[1]), "=r"(r[2]), "=r"(r[3]) : "r"(addr));
}
__device__ __forceinline__ void mma_h(float (&d)[4], const uint32_t* a, const uint32_t* b) {
    asm volatile("mma.sync.aligned.m16n8k16.row.col.f32.f16.f16.f32 "
                 "{%0,%1,%2,%3}, {%4,%5,%6,%7}, {%8,%9}, {%0,%1,%2,%3};"
                 : "+f"(d[0]), "+f"(d[1]), "+f"(d[2]), "+f"(d[3])
                 : "r"(a[0]), "r"(a[1]), "r"(a[2]), "r"(a[3]), "r"(b[0]), "r"(b[1]));
}
__device__ __forceinline__ uint32_t pkh(__half a, __half b) {
    return (uint32_t)__half_as_ushort(a) | ((uint32_t)__half_as_ushort(b) << 16);
}
__device__ __forceinline__ unsigned fkey(float x) {
    unsigned u = __float_as_uint(x);
    return (u & 0x80000000u) ? ~u : (u | 0x80000000u);
}
__device__ __forceinline__ float funkey(unsigned k) {
    unsigned u = (k & 0x80000000u) ? (k & 0x7FFFFFFFu) : ~k;
    return __uint_as_float(u);
}

/* ================= Kernel 0: fp32 -> fp16 splits (src: hi only; tgt: hi+lo) == */
__global__ __launch_bounds__(256)
void cvt_split(const float* __restrict__ src, const float* __restrict__ tgt)
{
    int i = blockIdx.x * 256 + threadIdx.x;        /* float4 index */
    if (blockIdx.y == 0) {
        float4 v = ((const float4*)src)[i];
        ((uint2*)g_Ah)[i] = make_uint2(
            pkh(__float2half_rn(v.x), __float2half_rn(v.y)),
            pkh(__float2half_rn(v.z), __float2half_rn(v.w)));
    } else {
        float4 v = ((const float4*)tgt)[i];
        __half hx = __float2half_rn(v.x), hy = __float2half_rn(v.y);
        __half hz = __float2half_rn(v.z), hw = __float2half_rn(v.w);
        ((uint2*)g_Bh)[i] = make_uint2(pkh(hx, hy), pkh(hz, hw));
        ((uint2*)g_Bl)[i] = make_uint2(
            pkh(__float2half_rn(v.x - __half2float(hx)), __float2half_rn(v.y - __half2float(hy))),
            pkh(__float2half_rn(v.z - __half2float(hz)), __float2half_rn(v.w - __half2float(hw))));
    }
}

/* ================= Kernel 1: fp16 2-term mma GEMM + fused masked softmax ======
   grid (32 M-tiles, 4 batches), 512 threads = 16 warps as 4(M) x 4(N).
   Warp tile 32x32. Ah (128x256) resident; B (hi+lo) streamed, 3-stage ring.   */
__global__ __launch_bounds__(512, 1)
void nce_gemm_mma(const int* __restrict__ cls)
{
    extern __shared__ __align__(1024) char smem[];
    const uint32_t sb = smem_u32(smem);
    const int tid = threadIdx.x, lane = tid & 31, w = tid >> 5;
    const int wm = w >> 2, wn = w & 3;
    const int b = blockIdx.y, mtB = blockIdx.x;
    const int R0 = b * NP + mtB * 128;
    const float NEGINF = __int_as_float(0xff800000);
    const float POSINF = __int_as_float(0x7f800000);
    int* scls = (int*)(smem + SM_CLS);

    /* ---- preload Ah: 4096 16B lines, swizzled chunk^row ---- */
#pragma unroll
    for (int q = 0; q < 8; q++) {
        int line = tid + q * 512;
        int mrow = line >> 5, c = line & 31;
        uint32_t dst = sb + SM_A + (uint32_t)mrow * 512u + (uint32_t)((c ^ (mrow & 7)) << 4);
        cp16(dst, g_Ah + (size_t)(R0 + mrow) * 128 + c * 4);
    }

    /* ---- B chunk loader: chunk i = (ct=i>>2, kc=i&3) ---- */
    auto loadB = [&](int i, int stage) {
        const int ct = i >> 2, kc = i & 3;
        const size_t rb = (size_t)(b * NP + ct * 128) * 128 + (size_t)kc * 32;
#pragma unroll
        for (int sp = 0; sp < 2; sp++) {
            const uint32_t* g = sp ? g_Bl : g_Bh;
            uint32_t dbase = sb + SM_B + (uint32_t)stage * 32768u + (uint32_t)sp * 16384u;
#pragma unroll
            for (int ii = 0; ii < 2; ii++) {
                int q = tid * 2 + ii;               /* 0..1023 */
                int n = q >> 3, c = q & 7;
                uint32_t dst = dbase + (uint32_t)n * 128u + (uint32_t)((c ^ (n & 7)) << 4);
                cp16(dst, g + rb + (size_t)n * 128 + c * 4);
            }
        }
    };
    loadB(0, 0); CP_COMMIT();
    loadB(1, 1); CP_COMMIT();

    /* ---- class table ---- */
#pragma unroll
    for (int q = 0; q < 2; q++)
        ((int4*)scls)[tid + q * 512] = ((const int4*)(cls + b * NP))[tid + q * 512];
    __syncthreads();

    int rcls[4];
#pragma unroll
    for (int j = 0; j < 4; j++)
        rcls[j] = scls[mtB * 128 + wm * 32 + (j >> 1) * 16 + (j & 1) * 8 + (lane >> 2)];

    float m_[4], s_[4], mn_[4];
#pragma unroll
    for (int j = 0; j < 4; j++) { m_[j] = NEGINF; s_[j] = 0.f; mn_[j] = POSINF; }

    const int la7 = lane & 7;
    const uint32_t aRowOff = (uint32_t)(wm * 32 + ((lane >> 3) & 1) * 8 + la7) * 512u;
    const int aKg = lane >> 4;
    const uint32_t bRowOff = (uint32_t)(wn * 32 + ((lane >> 4) & 1) * 8 + la7) * 128u;
    const int bKg = (lane >> 3) & 1;

    float acc[2][4][4];

#pragma unroll 1
    for (int i = 0; i < 128; i++) {
        if (i < 127) { CP_WAIT1(); } else { CP_WAIT0(); }
        __syncthreads();
        if (i < 126) { loadB(i + 2, (i + 2) % 3); CP_COMMIT(); }

        const int kc = i & 3, ct = i >> 2;
        const uint32_t Bst = sb + SM_B + (uint32_t)(i % 3) * 32768u;
        if (kc == 0) {
#pragma unroll
            for (int mt = 0; mt < 2; mt++)
#pragma unroll
                for (int nt = 0; nt < 4; nt++)
#pragma unroll
                    for (int j = 0; j < 4; j++) acc[mt][nt][j] = 0.f;
        }

#pragma unroll
        for (int ks = 0; ks < 4; ks++) {
            uint32_t ah[2][4];
#pragma unroll
            for (int mt = 0; mt < 2; mt++) {
                uint32_t ca = (uint32_t)((kc * 8 + ks * 2 + aKg) ^ la7) << 4;
                ldsm4(ah[mt], sb + SM_A + aRowOff + (uint32_t)mt * 8192u + ca);
            }
            uint32_t bh[2][4], bl[2][4];
#pragma unroll
            for (int p = 0; p < 2; p++) {
                uint32_t cb = (uint32_t)((ks * 2 + bKg) ^ la7) << 4;
                uint32_t base = Bst + bRowOff + (uint32_t)p * 2048u + cb;
                ldsm4(bh[p], base);
                ldsm4(bl[p], base + 16384u);
            }
#pragma unroll
            for (int mt = 0; mt < 2; mt++)
#pragma unroll
                for (int p = 0; p < 2; p++)
#pragma unroll
                    for (int hh = 0; hh < 2; hh++) {
                        int nt = p * 2 + hh;
                        mma_h(acc[mt][nt], ah[mt], &bh[p][hh * 2]);
                        mma_h(acc[mt][nt], ah[mt], &bl[p][hh * 2]);
                    }
        }

        if (kc == 3) {
            /* ---- masked online update for this 128-col tile ---- */
            const int colbase = ct * 128 + wn * 32 + (lane & 3) * 2;
            int ccls[8];
#pragma unroll
            for (int nt = 0; nt < 4; nt++) {
                ccls[nt * 2]     = scls[colbase + nt * 8];
                ccls[nt * 2 + 1] = scls[colbase + nt * 8 + 1];
            }
#pragma unroll
            for (int j = 0; j < 4; j++) {
                const int mt = j >> 1, hh = j & 1;
                float tmax = NEGINF;
#pragma unroll
                for (int nt = 0; nt < 4; nt++) {
                    float l0 = acc[mt][nt][hh * 2], l1 = acc[mt][nt][hh * 2 + 1];
                    if (ccls[nt * 2] != rcls[j])     { mn_[j] = fminf(mn_[j], l0); tmax = fmaxf(tmax, l0); }
                    if (ccls[nt * 2 + 1] != rcls[j]) { mn_[j] = fminf(mn_[j], l1); tmax = fmaxf(tmax, l1); }
                }
                if (tmax != NEGINF) {
                    float nm = fmaxf(m_[j], tmax * CQ);
                    float a0 = 0.f, a1 = 0.f;
#pragma unroll
                    for (int nt = 0; nt < 4; nt++) {
                        float l0 = acc[mt][nt][hh * 2], l1 = acc[mt][nt][hh * 2 + 1];
                        a0 += ex2f((ccls[nt * 2] != rcls[j])     ? l0 * CQ - nm : NEGINF);
                        a1 += ex2f((ccls[nt * 2 + 1] != rcls[j]) ? l1 * CQ - nm : NEGINF);
                    }
                    s_[j] = s_[j] * ex2f(m_[j] - nm) + a0 + a1;
                    m_[j] = nm;
                }
            }
        }
    }

    /* ---- merge across the 4 lanes sharing each row ---- */
#pragma unroll
    for (int j = 0; j < 4; j++) {
#pragma unroll
        for (int d = 1; d <= 2; d <<= 1) {
            float om = __shfl_xor_sync(0xFFFFFFFFu, m_[j], d);
            float os = __shfl_xor_sync(0xFFFFFFFFu, s_[j], d);
            float on = __shfl_xor_sync(0xFFFFFFFFu, mn_[j], d);
            float nm = fmaxf(m_[j], om);
            float t0 = (m_[j] == NEGINF) ? 0.f : s_[j] * ex2f(m_[j] - nm);
            float t1 = (om == NEGINF) ? 0.f : os * ex2f(om - nm);
            s_[j] = t0 + t1; m_[j] = nm; mn_[j] = fminf(mn_[j], on);
        }
    }

    /* ---- cross-warp (wn 0..3) merge via SMEM (reuse B region) ---- */
    __syncthreads();
    float* mgM = (float*)(smem + SM_B);        /* [4][128] */
    float* mgS = mgM + 512;
    float* mgN = mgS + 512;
    if ((lane & 3) == 0) {
#pragma unroll
        for (int j = 0; j < 4; j++) {
            int row = wm * 32 + (j >> 1) * 16 + (j & 1) * 8 + (lane >> 2);
            mgM[wn * 128 + row] = m_[j];
            mgS[wn * 128 + row] = s_[j];
            mgN[wn * 128 + row] = mn_[j];
        }
    }
    __syncthreads();
    if (tid < 128) {
        float M = NEGINF, S = 0.f, MN = POSINF;
#pragma unroll
        for (int t = 0; t < 4; t++) M = fmaxf(M, mgM[t * 128 + tid]);
        if (M != NEGINF) {
#pragma unroll
            for (int t = 0; t < 4; t++) {
                float mt_ = mgM[t * 128 + tid];
                if (mt_ != NEGINF) S += mgS[t * 128 + tid] * ex2f(mt_ - M);
            }
        }
#pragma unroll
        for (int t = 0; t < 4; t++) MN = fminf(MN, mgN[t * 128 + tid]);
        g_m [R0 + tid] = M;
        g_s [R0 + tid] = S;
        g_mn[R0 + tid] = MN;
    }
}

/* ================= Kernel 2a: per-chunk hist + class-min (parallel) ========== */
__global__ void nce_hist(const int* __restrict__ cls)
{
    __shared__ int      h[NC];
    __shared__ unsigned mk[NC];
    const int ch = blockIdx.x, b = blockIdx.y, tid = threadIdx.x;
    if (tid < NC) { h[tid] = 0; mk[tid] = 0xFF800000u; /* fkey(+inf) */ }
    __syncthreads();
    const int row = b * NP + ch * 128 + tid;
    const int c = cls[row];
    atomicAdd(&h[c], 1);
    atomicMin(&mk[c], fkey(g_mn[row]));
    __syncthreads();
    if (tid < NC) { g_hist[b][ch][tid] = h[tid]; g_chmin[b][ch][tid] = mk[tid]; }
}

/* ================= Kernel 2b: counts / smallest / chunk prefix =============== */
__global__ void nce_pref()
{
    const int b = blockIdx.x, tid = threadIdx.x;
    __shared__ int cnt_s[NC];
    if (tid < NC) {
        int cnt = 0; unsigned mn = 0xFF800000u;
        for (int ch = 0; ch < 32; ch++) {
            cnt += g_hist[b][ch][tid];
            mn = min(mn, g_chmin[b][ch][tid]);
        }
        cnt_s[tid] = cnt;
        g_counts[b][tid] = cnt;
        g_smallest[b][tid] = fminf(funkey(mn), -10.0f) * INV_T;
    }
    __syncthreads();
    if (tid < NC) {
        int run = 0;
        for (int c2 = 0; c2 < tid; c2++) run += cnt_s[c2];
        for (int ch = 0; ch < 32; ch++) { g_chunkpref[b][ch][tid] = run; run += g_hist[b][ch][tid]; }
    }
}

/* ================= Kernel 3: final 3-way LSE + stable class-sorted scatter === */
__global__ void nce_final(const float* __restrict__ src, const float* __restrict__ tgt,
                          const int* __restrict__ cls, float* __restrict__ out)
{
    const int ch = blockIdx.x, b = blockIdx.y, tid = threadIdx.x;
    const int lane = tid & 31, w = tid >> 5;
    const int row = b * NP + ch * 128 + tid;
    const float NEGINF = __int_as_float(0xff800000);

    __shared__ int wcnt[4][NC];
    const int c = cls[row];

    /* rank within warp among same-class lanes */
    unsigned match = __match_any_sync(0xFFFFFFFFu, c);
    int lr = __popc(match & ((1u << lane) - 1u));
    /* per-warp class counts */
#pragma unroll
    for (int c2 = 0; c2 < NC; c2++) {
        unsigned bal = __ballot_sync(0xFFFFFFFFu, c == c2);
        if (lane == c2) wcnt[w][c2] = __popc(bal);
    }
    __syncthreads();
    for (int w2 = 0; w2 < w; w2++) lr += wcnt[w2][c];
    const int opos = b * NP + g_chunkpref[b][ch][c] + lr;

    const float4* s4 = (const float4*)(src + (size_t)row * DIM);
    const float4* t4 = (const float4*)(tgt + (size_t)row * DIM);
    float p0 = 0.f, p1 = 0.f, p2 = 0.f, p3 = 0.f;
#pragma unroll
    for (int d = 0; d < 64; d++) {
        float4 a = s4[d], v = t4[d];
        p0 += a.x * v.x; p1 += a.y * v.y; p2 += a.z * v.z; p3 += a.w * v.w;
    }
    const float pos_n = (p0 + p1 + p2 + p3) * INV_T;

    const float M = g_m[row], S = g_s[row];
    const float lneg = (S > 0.f) ? (M * LN2F + logf(S)) : NEGINF;

    const int   npad = g_counts[b][c] - 1;
    const float pad  = (npad > 0) ? (logf((float)npad) + g_smallest[b][c]) : NEGINF;

    const float Mx  = fmaxf(pos_n, fmaxf(lneg, pad));
    const float sum = expf(pos_n - Mx) + expf(lneg - Mx) + expf(pad - Mx);
    out[opos] = Mx + logf(sum) - pos_n;
}

/* ============================================================================ */
extern "C" void kernel_launch(void* const* d_in, const int* in_sizes, int n_in,
                              void* d_out, int out_size)
{
    const float* src = (const float*)d_in[0];
    const float* tgt = (const float*)d_in[1];
    const int*   cls = (const int*)d_in[2];
    float*       out = (float*)d_out;

    cudaFuncSetAttribute(nce_gemm_mma, cudaFuncAttributeMaxDynamicSharedMemorySize, SMEM_BYTES);

    cvt_split<<<dim3(NROWS * DIM / 4 / 256, 2), 256>>>(src, tgt);
    nce_gemm_mma<<<dim3(32, NBATCH), 512, SMEM_BYTES>>>(cls);
    nce_hist<<<dim3(32, NBATCH), 128>>>(cls);
    nce_pref<<<NBATCH, 32>>>();
    nce_final<<<dim3(32, NBATCH), 128>>>(src, tgt, cls, out);
}

// round 8
// speedup vs baseline: 5.7840x; 1.0156x over previous
#include <cuda_runtime.h>
#include <cuda_fp16.h>
#include <cstdint>

#define NBATCH 4
#define NP     4096
#define DIM    256
#define NC     5
#define NROWS  (NBATCH * NP)

#define INV_T  14.285714285714286f            /* 1/0.07 */
#define CQ     20.60992915555662f             /* log2(e)/0.07 */
#define LN2F   0.6931471805599453f

/* ---- SMEM layout (bytes) ---- */
#define SM_A     0          /* Ah: 128 rows x 512B, swizzled (64 KB) */
#define SM_B     65536      /* 3 stages x (Bh 16384 + Bl 16384) = 96 KB */
#define SM_CLS   163840     /* 4096 ints */
#define SMEM_BYTES 180224

/* ---- persistent scratch (no allocations allowed) ---- */
__device__ uint32_t g_Ah[NROWS * DIM / 2];   /* src hi (fp16x2-packed) */
__device__ uint32_t g_Bh[NROWS * DIM / 2];   /* tgt hi */
__device__ uint32_t g_Bl[NROWS * DIM / 2];   /* tgt lo */
__device__ float g_m [NROWS];
__device__ float g_s [NROWS];
__device__ int      g_hist [NBATCH][32][NC];
__device__ unsigned g_chmin[NBATCH][32][NC];

/* ================= helpers ================= */
__device__ __forceinline__ uint32_t smem_u32(const void* p) {
    uint32_t a;
    asm("{ .reg .u64 t; cvta.to.shared.u64 t, %1; cvt.u32.u64 %0, t; }" : "=r"(a) : "l"(p));
    return a;
}
__device__ __forceinline__ float ex2f(float x) {
    float y; asm("ex2.approx.ftz.f32 %0, %1;" : "=f"(y) : "f"(x)); return y;
}
__device__ __forceinline__ void cp16(uint32_t dst, const void* src) {
    asm volatile("cp.async.cg.shared.global [%0], [%1], 16;" :: "r"(dst), "l"(src));
}
#define CP_COMMIT() asm volatile("cp.async.commit_group;" ::: "memory")
#define CP_WAIT1()  asm volatile("cp.async.wait_group 1;" ::: "memory")
#define CP_WAIT0()  asm volatile("cp.async.wait_group 0;" ::: "memory")

__device__ __forceinline__ void ldsm4(uint32_t (&r)[4], uint32_t addr) {
    asm volatile("ldmatrix.sync.aligned.m8n8.x4.shared.b16 {%0,%1,%2,%3}, [%4];"
                 : "=r"(r[0]), "=r"(r[1]), "=r"(r[2]), "=r"(r[3]) : "r"(addr));
}
__device__ __forceinline__ void mma_h(float (&d)[4], const uint32_t* a, const uint32_t* b) {
    asm volatile("mma.sync.aligned.m16n8k16.row.col.f32.f16.f16.f32 "
                 "{%0,%1,%2,%3}, {%4,%5,%6,%7}, {%8,%9}, {%0,%1,%2,%3};"
                 : "+f"(d[0]), "+f"(d[1]), "+f"(d[2]), "+f"(d[3])
                 : "r"(a[0]), "r"(a[1]), "r"(a[2]), "r"(a[3]), "r"(b[0]), "r"(b[1]));
}
__device__ __forceinline__ uint32_t pkh(__half a, __half b) {
    return (uint32_t)__half_as_ushort(a) | ((uint32_t)__half_as_ushort(b) << 16);
}
__device__ __forceinline__ unsigned fkey(float x) {
    unsigned u = __float_as_uint(x);
    return (u & 0x80000000u) ? ~u : (u | 0x80000000u);
}
__device__ __forceinline__ float funkey(unsigned k) {
    unsigned u = (k & 0x80000000u) ? (k & 0x7FFFFFFFu) : ~k;
    return __uint_as_float(u);
}

/* ================= Kernel 0: fp32 -> fp16 splits (src: hi only; tgt: hi+lo) == */
__global__ __launch_bounds__(256)
void cvt_split(const float* __restrict__ src, const float* __restrict__ tgt)
{
    int i = blockIdx.x * 256 + threadIdx.x;        /* float4 index */
    if (blockIdx.y == 0) {
        float4 v = ((const float4*)src)[i];
        ((uint2*)g_Ah)[i] = make_uint2(
            pkh(__float2half_rn(v.x), __float2half_rn(v.y)),
            pkh(__float2half_rn(v.z), __float2half_rn(v.w)));
    } else {
        float4 v = ((const float4*)tgt)[i];
        __half hx = __float2half_rn(v.x), hy = __float2half_rn(v.y);
        __half hz = __float2half_rn(v.z), hw = __float2half_rn(v.w);
        ((uint2*)g_Bh)[i] = make_uint2(pkh(hx, hy), pkh(hz, hw));
        ((uint2*)g_Bl)[i] = make_uint2(
            pkh(__float2half_rn(v.x - __half2float(hx)), __float2half_rn(v.y - __half2float(hy))),
            pkh(__float2half_rn(v.z - __half2float(hz)), __float2half_rn(v.w - __half2float(hw))));
    }
}

/* ================= Kernel 1: fp16 2-term mma GEMM + fused masked softmax ======
   grid (32 M-tiles, 4 batches), 512 threads = 16 warps as 4(M) x 4(N).
   Warp tile 32x32. Ah (128x256) resident; B (hi+lo) streamed, 3-stage ring.
   Also emits per-chunk class histogram + class-min (replaces nce_hist).       */
__global__ __launch_bounds__(512, 1)
void nce_gemm_mma(const int* __restrict__ cls)
{
    extern __shared__ __align__(1024) char smem[];
    const uint32_t sb = smem_u32(smem);
    const int tid = threadIdx.x, lane = tid & 31, w = tid >> 5;
    const int wm = w >> 2, wn = w & 3;
    const int b = blockIdx.y, mtB = blockIdx.x;
    const int R0 = b * NP + mtB * 128;
    const float NEGINF = __int_as_float(0xff800000);
    const float POSINF = __int_as_float(0x7f800000);
    int* scls = (int*)(smem + SM_CLS);

    __shared__ int      sh_h[NC];
    __shared__ unsigned sh_mk[NC];
    if (tid < NC) { sh_h[tid] = 0; sh_mk[tid] = 0xFF800000u; /* fkey(+inf) */ }

    /* ---- preload Ah: 4096 16B lines, swizzled chunk^row ---- */
#pragma unroll
    for (int q = 0; q < 8; q++) {
        int line = tid + q * 512;
        int mrow = line >> 5, c = line & 31;
        uint32_t dst = sb + SM_A + (uint32_t)mrow * 512u + (uint32_t)((c ^ (mrow & 7)) << 4);
        cp16(dst, g_Ah + (size_t)(R0 + mrow) * 128 + c * 4);
    }

    /* ---- B chunk loader: chunk i = (ct=i>>2, kc=i&3) ---- */
    auto loadB = [&](int i, int stage) {
        const int ct = i >> 2, kc = i & 3;
        const size_t rb = (size_t)(b * NP + ct * 128) * 128 + (size_t)kc * 32;
#pragma unroll
        for (int sp = 0; sp < 2; sp++) {
            const uint32_t* g = sp ? g_Bl : g_Bh;
            uint32_t dbase = sb + SM_B + (uint32_t)stage * 32768u + (uint32_t)sp * 16384u;
#pragma unroll
            for (int ii = 0; ii < 2; ii++) {
                int q = tid * 2 + ii;               /* 0..1023 */
                int n = q >> 3, c = q & 7;
                uint32_t dst = dbase + (uint32_t)n * 128u + (uint32_t)((c ^ (n & 7)) << 4);
                cp16(dst, g + rb + (size_t)n * 128 + c * 4);
            }
        }
    };
    loadB(0, 0); CP_COMMIT();
    loadB(1, 1); CP_COMMIT();

    /* ---- class table ---- */
#pragma unroll
    for (int q = 0; q < 2; q++)
        ((int4*)scls)[tid + q * 512] = ((const int4*)(cls + b * NP))[tid + q * 512];
    __syncthreads();

    int rcls[4];
#pragma unroll
    for (int j = 0; j < 4; j++)
        rcls[j] = scls[mtB * 128 + wm * 32 + (j >> 1) * 16 + (j & 1) * 8 + (lane >> 2)];

    float m_[4], s_[4], mn_[4];
#pragma unroll
    for (int j = 0; j < 4; j++) { m_[j] = NEGINF; s_[j] = 0.f; mn_[j] = POSINF; }

    const int la7 = lane & 7;
    const uint32_t aRowOff = (uint32_t)(wm * 32 + ((lane >> 3) & 1) * 8 + la7) * 512u;
    const int aKg = lane >> 4;
    const uint32_t bRowOff = (uint32_t)(wn * 32 + ((lane >> 4) & 1) * 8 + la7) * 128u;
    const int bKg = (lane >> 3) & 1;

    float acc[2][4][4];

#pragma unroll 1
    for (int ct = 0; ct < 32; ct++) {
#pragma unroll
        for (int mt = 0; mt < 2; mt++)
#pragma unroll
            for (int nt = 0; nt < 4; nt++)
#pragma unroll
                for (int j = 0; j < 4; j++) acc[mt][nt][j] = 0.f;

#pragma unroll
        for (int kc = 0; kc < 4; kc++) {
            const int i = ct * 4 + kc;
            if (i == 127) { CP_WAIT0(); } else { CP_WAIT1(); }
            __syncthreads();
            if (i < 126) { loadB(i + 2, (i + 2) % 3); CP_COMMIT(); }
            const uint32_t Bst = sb + SM_B + (uint32_t)(i % 3) * 32768u;

#pragma unroll
            for (int ks = 0; ks < 4; ks++) {
                uint32_t ah[2][4];
#pragma unroll
                for (int mt = 0; mt < 2; mt++) {
                    uint32_t ca = (uint32_t)((kc * 8 + ks * 2 + aKg) ^ la7) << 4;
                    ldsm4(ah[mt], sb + SM_A + aRowOff + (uint32_t)mt * 8192u + ca);
                }
                uint32_t bh[2][4], bl[2][4];
#pragma unroll
                for (int p = 0; p < 2; p++) {
                    uint32_t cb = (uint32_t)((ks * 2 + bKg) ^ la7) << 4;
                    uint32_t base = Bst + bRowOff + (uint32_t)p * 2048u + cb;
                    ldsm4(bh[p], base);
                    ldsm4(bl[p], base + 16384u);
                }
#pragma unroll
                for (int mt = 0; mt < 2; mt++)
#pragma unroll
                    for (int p = 0; p < 2; p++)
#pragma unroll
                        for (int hh = 0; hh < 2; hh++) {
                            int nt = p * 2 + hh;
                            mma_h(acc[mt][nt], ah[mt], &bh[p][hh * 2]);
                            mma_h(acc[mt][nt], ah[mt], &bl[p][hh * 2]);
                        }
            }
        }

        /* ---- masked online update for this 128-col tile ---- */
        const int colbase = ct * 128 + wn * 32 + (lane & 3) * 2;
        int ccls[8];
#pragma unroll
        for (int nt = 0; nt < 4; nt++) {
            ccls[nt * 2]     = scls[colbase + nt * 8];
            ccls[nt * 2 + 1] = scls[colbase + nt * 8 + 1];
        }
#pragma unroll
        for (int j = 0; j < 4; j++) {
            const int mt = j >> 1, hh = j & 1;
            float tmax = NEGINF;
#pragma unroll
            for (int nt = 0; nt < 4; nt++) {
                float l0 = acc[mt][nt][hh * 2], l1 = acc[mt][nt][hh * 2 + 1];
                if (ccls[nt * 2] != rcls[j])     { mn_[j] = fminf(mn_[j], l0); tmax = fmaxf(tmax, l0); }
                if (ccls[nt * 2 + 1] != rcls[j]) { mn_[j] = fminf(mn_[j], l1); tmax = fmaxf(tmax, l1); }
            }
            if (tmax != NEGINF) {
                float nm = fmaxf(m_[j], tmax * CQ);
                float a0 = 0.f, a1 = 0.f;
#pragma unroll
                for (int nt = 0; nt < 4; nt++) {
                    float l0 = acc[mt][nt][hh * 2], l1 = acc[mt][nt][hh * 2 + 1];
                    a0 += ex2f((ccls[nt * 2] != rcls[j])     ? l0 * CQ - nm : NEGINF);
                    a1 += ex2f((ccls[nt * 2 + 1] != rcls[j]) ? l1 * CQ - nm : NEGINF);
                }
                s_[j] = s_[j] * ex2f(m_[j] - nm) + a0 + a1;
                m_[j] = nm;
            }
        }
    }

    /* ---- merge across the 4 lanes sharing each row ---- */
#pragma unroll
    for (int j = 0; j < 4; j++) {
#pragma unroll
        for (int d = 1; d <= 2; d <<= 1) {
            float om = __shfl_xor_sync(0xFFFFFFFFu, m_[j], d);
            float os = __shfl_xor_sync(0xFFFFFFFFu, s_[j], d);
            float on = __shfl_xor_sync(0xFFFFFFFFu, mn_[j], d);
            float nm = fmaxf(m_[j], om);
            float t0 = (m_[j] == NEGINF) ? 0.f : s_[j] * ex2f(m_[j] - nm);
            float t1 = (om == NEGINF) ? 0.f : os * ex2f(om - nm);
            s_[j] = t0 + t1; m_[j] = nm; mn_[j] = fminf(mn_[j], on);
        }
    }

    /* ---- cross-warp (wn 0..3) merge via SMEM (reuse B region) ---- */
    __syncthreads();
    float* mgM = (float*)(smem + SM_B);        /* [4][128] */
    float* mgS = mgM + 512;
    float* mgN = mgS + 512;
    if ((lane & 3) == 0) {
#pragma unroll
        for (int j = 0; j < 4; j++) {
            int row = wm * 32 + (j >> 1) * 16 + (j & 1) * 8 + (lane >> 2);
            mgM[wn * 128 + row] = m_[j];
            mgS[wn * 128 + row] = s_[j];
            mgN[wn * 128 + row] = mn_[j];
        }
    }
    __syncthreads();
    if (tid < 128) {
        float M = NEGINF, S = 0.f, MN = POSINF;
#pragma unroll
        for (int t = 0; t < 4; t++) M = fmaxf(M, mgM[t * 128 + tid]);
        if (M != NEGINF) {
#pragma unroll
            for (int t = 0; t < 4; t++) {
                float mt_ = mgM[t * 128 + tid];
                if (mt_ != NEGINF) S += mgS[t * 128 + tid] * ex2f(mt_ - M);
            }
        }
#pragma unroll
        for (int t = 0; t < 4; t++) MN = fminf(MN, mgN[t * 128 + tid]);
        g_m[R0 + tid] = M;
        g_s[R0 + tid] = S;
        /* per-chunk class histogram + class-min (was nce_hist) */
        int c = scls[mtB * 128 + tid];
        atomicAdd(&sh_h[c], 1);
        atomicMin(&sh_mk[c], fkey(MN));
    }
    __syncthreads();
    if (tid < NC) {
        g_hist [b][mtB][tid] = sh_h[tid];
        g_chmin[b][mtB][tid] = sh_mk[tid];
    }
}

/* ================= Kernel 2: final 3-way LSE + stable class-sorted scatter ===
   Also computes counts / smallest / chunk-prefix from g_hist/g_chmin
   (was nce_pref) — 320 ints per block from L2.                               */
__global__ void nce_final(const float* __restrict__ src, const float* __restrict__ tgt,
                          const int* __restrict__ cls, float* __restrict__ out)
{
    const int ch = blockIdx.x, b = blockIdx.y, tid = threadIdx.x;
    const int lane = tid & 31, w = tid >> 5;
    const int row = b * NP + ch * 128 + tid;
    const float NEGINF = __int_as_float(0xff800000);

    __shared__ int      hist_s[32][NC];
    __shared__ unsigned chm_s [32][NC];
    __shared__ int      pref_s[NC];     /* chunk-prefix for this ch */
    __shared__ int      cnt_s [NC];
    __shared__ float    small_s[NC];
    __shared__ int      wcnt[4][NC];

    for (int i = tid; i < 32 * NC; i += 128) {
        ((int*)hist_s)[i]      = ((const int*)g_hist [b])[i];
        ((unsigned*)chm_s)[i]  = ((const unsigned*)g_chmin[b])[i];
    }
    __syncthreads();
    if (tid < NC) {
        int run = 0, mypref = 0;
        unsigned mn = 0xFF800000u;
        for (int h2 = 0; h2 < 32; h2++) {
            if (h2 == ch) mypref = run;
            run += hist_s[h2][tid];
            mn = min(mn, chm_s[h2][tid]);
        }
        pref_s[tid] = mypref;
        cnt_s[tid] = run;
        small_s[tid] = fminf(funkey(mn), -10.0f) * INV_T;
    }

    const int c = cls[row];
    /* rank within warp among same-class lanes */
    unsigned match = __match_any_sync(0xFFFFFFFFu, c);
    int lr = __popc(match & ((1u << lane) - 1u));
#pragma unroll
    for (int c2 = 0; c2 < NC; c2++) {
        unsigned bal = __ballot_sync(0xFFFFFFFFu, c == c2);
        if (lane == c2) wcnt[w][c2] = __popc(bal);
    }
    __syncthreads();
    for (int w2 = 0; w2 < w; w2++) lr += wcnt[w2][c];
    int classpref = 0;
    for (int c2 = 0; c2 < c; c2++) classpref += cnt_s[c2];
    const int opos = b * NP + classpref + pref_s[c] + lr;

    const float4* s4 = (const float4*)(src + (size_t)row * DIM);
    const float4* t4 = (const float4*)(tgt + (size_t)row * DIM);
    float p0 = 0.f, p1 = 0.f, p2 = 0.f, p3 = 0.f;
#pragma unroll
    for (int d = 0; d < 64; d++) {
        float4 a = s4[d], v = t4[d];
        p0 += a.x * v.x; p1 += a.y * v.y; p2 += a.z * v.z; p3 += a.w * v.w;
    }
    const float pos_n = (p0 + p1 + p2 + p3) * INV_T;

    const float M = g_m[row], S = g_s[row];
    const float lneg = (S > 0.f) ? (M * LN2F + logf(S)) : NEGINF;

    const int   npad = cnt_s[c] - 1;
    const float pad  = (npad > 0) ? (logf((float)npad) + small_s[c]) : NEGINF;

    const float Mx  = fmaxf(pos_n, fmaxf(lneg, pad));
    const float sum = expf(pos_n - Mx) + expf(lneg - Mx) + expf(pad - Mx);
    out[opos] = Mx + logf(sum) - pos_n;
}

/* ============================================================================ */
extern "C" void kernel_launch(void* const* d_in, const int* in_sizes, int n_in,
                              void* d_out, int out_size)
{
    const float* src = (const float*)d_in[0];
    const float* tgt = (const float*)d_in[1];
    const int*   cls = (const int*)d_in[2];
    float*       out = (float*)d_out;

    cudaFuncSetAttribute(nce_gemm_mma, cudaFuncAttributeMaxDynamicSharedMemorySize, SMEM_BYTES);

    cvt_split<<<dim3(NROWS * DIM / 4 / 256, 2), 256>>>(src, tgt);
    nce_gemm_mma<<<dim3(32, NBATCH), 512, SMEM_BYTES>>>(cls);
    nce_final<<<dim3(32, NBATCH), 128>>>(src, tgt, cls, out);
}

// round 9
// speedup vs baseline: 5.8383x; 1.0094x over previous
#include <cuda_runtime.h>
#include <cuda_fp16.h>
#include <cstdint>

#define NBATCH 4
#define NP     4096
#define DIM    256
#define NC     5
#define NROWS  (NBATCH * NP)

#define INV_T  14.285714285714286f            /* 1/0.07 */
#define CQ     20.60992915555662f             /* log2(e)/0.07 */
#define LN2F   0.6931471805599453f

/* ---- SMEM layout (bytes) ---- */
#define SM_A     0          /* Ah: 128 rows x 512B, swizzled (64 KB) */
#define SM_B     65536      /* 3 stages x (Bh 16384 + Bl 16384) = 96 KB; stage = 256 rows x 64B */
#define SM_CLS   163840     /* 4096 ints */
#define SMEM_BYTES 180224

/* ---- persistent scratch (no allocations allowed) ---- */
__device__ uint32_t g_Bh[NROWS * DIM / 2];   /* tgt hi (fp16x2-packed) */
__device__ uint32_t g_Bl[NROWS * DIM / 2];   /* tgt lo */
__device__ float g_m [NROWS];
__device__ float g_s [NROWS];
__device__ int      g_hist [NBATCH][32][NC];
__device__ unsigned g_chmin[NBATCH][32][NC];

/* ================= helpers ================= */
__device__ __forceinline__ uint32_t smem_u32(const void* p) {
    uint32_t a;
    asm("{ .reg .u64 t; cvta.to.shared.u64 t, %1; cvt.u32.u64 %0, t; }" : "=r"(a) : "l"(p));
    return a;
}
__device__ __forceinline__ float ex2f(float x) {
    float y; asm("ex2.approx.ftz.f32 %0, %1;" : "=f"(y) : "f"(x)); return y;
}
__device__ __forceinline__ void cp16(uint32_t dst, const void* src) {
    asm volatile("cp.async.cg.shared.global [%0], [%1], 16;" :: "r"(dst), "l"(src));
}
#define CP_COMMIT() asm volatile("cp.async.commit_group;" ::: "memory")
#define CP_WAIT1()  asm volatile("cp.async.wait_group 1;" ::: "memory")
#define CP_WAIT0()  asm volatile("cp.async.wait_group 0;" ::: "memory")

__device__ __forceinline__ void ldsm4(uint32_t (&r)[4], uint32_t addr) {
    asm volatile("ldmatrix.sync.aligned.m8n8.x4.shared.b16 {%0,%1,%2,%3}, [%4];"
                 : "=r"(r[0]), "=r"(r[1]), "=r"(r[2]), "=r"(r[3]) : "r"(addr));
}
__device__ __forceinline__ void mma_h(float (&d)[4], const uint32_t* a, const uint32_t* b) {
    asm volatile("mma.sync.aligned.m16n8k16.row.col.f32.f16.f16.f32 "
                 "{%0,%1,%2,%3}, {%4,%5,%6,%7}, {%8,%9}, {%0,%1,%2,%3};"
                 : "+f"(d[0]), "+f"(d[1]), "+f"(d[2]), "+f"(d[3])
                 : "r"(a[0]), "r"(a[1]), "r"(a[2]), "r"(a[3]), "r"(b[0]), "r"(b[1]));
}
__device__ __forceinline__ uint32_t pkh(__half a, __half b) {
    return (uint32_t)__half_as_ushort(a) | ((uint32_t)__half_as_ushort(b) << 16);
}
__device__ __forceinline__ unsigned fkey(float x) {
    unsigned u = __float_as_uint(x);
    return (u & 0x80000000u) ? ~u : (u | 0x80000000u);
}
__device__ __forceinline__ float funkey(unsigned k) {
    unsigned u = (k & 0x80000000u) ? (k & 0x7FFFFFFFu) : ~k;
    return __uint_as_float(u);
}

/* ================= Kernel 0: tgt fp32 -> fp16 hi/lo splits ================= */
__global__ __launch_bounds__(256)
void cvt_split(const float* __restrict__ tgt)
{
    int i = blockIdx.x * 256 + threadIdx.x;        /* float4 index */
    float4 v = ((const float4*)tgt)[i];
    __half hx = __float2half_rn(v.x), hy = __float2half_rn(v.y);
    __half hz = __float2half_rn(v.z), hw = __float2half_rn(v.w);
    ((uint2*)g_Bh)[i] = make_uint2(pkh(hx, hy), pkh(hz, hw));
    ((uint2*)g_Bl)[i] = make_uint2(
        pkh(__float2half_rn(v.x - __half2float(hx)), __float2half_rn(v.y - __half2float(hy))),
        pkh(__float2half_rn(v.z - __half2float(hz)), __float2half_rn(v.w - __half2float(hw))));
}

/* ================= Kernel 1: fp16 2-term mma GEMM + fused masked softmax ======
   grid (32 M-tiles, 4 batches), 512 threads = 16 warps as 2(M) x 8(N).
   Warp tile 64x32. CTA N-tile 256 cols per iteration-tile. A converted fp32->
   fp16 in prologue, resident in SMEM. B hi+lo streamed in 32-k stages, 3-ring.
   Emits per-chunk class histogram + class-min.                                */
__global__ __launch_bounds__(512, 1)
void nce_gemm_mma(const float* __restrict__ src, const int* __restrict__ cls)
{
    extern __shared__ __align__(1024) char smem[];
    const uint32_t sb = smem_u32(smem);
    const int tid = threadIdx.x, lane = tid & 31, w = tid >> 5;
    const int wm = w >> 3, wn = w & 7;
    const int b = blockIdx.y, mtB = blockIdx.x;
    const int R0 = b * NP + mtB * 128;
    const float NEGINF = __int_as_float(0xff800000);
    const float POSINF = __int_as_float(0x7f800000);
    int* scls = (int*)(smem + SM_CLS);

    __shared__ int      sh_h[NC];
    __shared__ unsigned sh_mk[NC];
    if (tid < NC) { sh_h[tid] = 0; sh_mk[tid] = 0xFF800000u; /* fkey(+inf) */ }

    /* ---- B stage loader: tile i = (ct=i>>3 [256 rows], kc=i&7 [32 k]) ---- */
    auto loadB = [&](int i, int stage) {
        const int ct = i >> 3, kc = i & 7;
        const uint32_t* __restrict__ gh = g_Bh + (size_t)(b * NP + ct * 256) * 128 + kc * 16;
        const uint32_t* __restrict__ gl = g_Bl + (size_t)(b * NP + ct * 256) * 128 + kc * 16;
        const uint32_t dbase = sb + SM_B + (uint32_t)stage * 32768u;
#pragma unroll
        for (int q = 0; q < 4; q++) {
            int idx = tid + q * 512;                 /* 0..2047 */
            int sp = idx >> 10, li = idx & 1023;
            int n = li >> 2, c = li & 3;
            int fn = (n + (n >> 2)) & 3;
            uint32_t dst = dbase + (uint32_t)sp * 16384u + (uint32_t)n * 64u
                         + (uint32_t)((c ^ fn) << 4);
            cp16(dst, (sp ? gl : gh) + (size_t)n * 128 + c * 4);
        }
    };
    loadB(0, 0); CP_COMMIT();
    loadB(1, 1); CP_COMMIT();

    /* ---- A prologue: fp32 rows -> fp16, swizzled STS (row*512 + (c^row&7)*16) */
    {
        const float4* Ag = (const float4*)(src + (size_t)R0 * DIM);
#pragma unroll
        for (int q = 0; q < 8; q++) {
            int line = tid + q * 512;               /* 0..4095 */
            int row = line >> 5, c = line & 31;
            float4 v0 = Ag[row * 64 + c * 2];
            float4 v1 = Ag[row * 64 + c * 2 + 1];
            uint4 h = make_uint4(pkh(__float2half_rn(v0.x), __float2half_rn(v0.y)),
                                 pkh(__float2half_rn(v0.z), __float2half_rn(v0.w)),
                                 pkh(__float2half_rn(v1.x), __float2half_rn(v1.y)),
                                 pkh(__float2half_rn(v1.z), __float2half_rn(v1.w)));
            *(uint4*)(smem + SM_A + row * 512 + ((c ^ (row & 7)) << 4)) = h;
        }
    }

    /* ---- class table ---- */
#pragma unroll
    for (int q = 0; q < 2; q++)
        ((int4*)scls)[tid + q * 512] = ((const int4*)(cls + b * NP))[tid + q * 512];

    /* ---- per-lane constants ---- */
    const int la7 = lane & 7;
    const int aRowBase = wm * 64 + ((lane >> 3) & 1) * 8 + la7;    /* + mt*16 */
    const uint32_t aOff = sb + SM_A + (uint32_t)aRowBase * 512u;
    const int a7s = aRowBase & 7;
    const int aKg = lane >> 4;                                     /* k8 group */
    const int nB = wn * 32 + ((lane >> 4) & 1) * 8 + la7;          /* + p*16 */
    const uint32_t bOff = (uint32_t)nB * 64u;
    const int fnB = (nB + (nB >> 2)) & 3;
    const int bKg = (lane >> 3) & 1;

    float m_[8], s_[8], mn_[8];
#pragma unroll
    for (int j = 0; j < 8; j++) { m_[j] = NEGINF; s_[j] = 0.f; mn_[j] = POSINF; }

    float acc[4][4][4];

    /* ---- epilogue: masked online update over this 256-col tile ---- */
    auto epilogue = [&](int ct) {
        const int cb = ct * 256 + wn * 32 + (lane & 3) * 2;
        int ccls[8];
#pragma unroll
        for (int nt = 0; nt < 4; nt++) {
            ccls[nt * 2]     = scls[cb + nt * 8];
            ccls[nt * 2 + 1] = scls[cb + nt * 8 + 1];
        }
#pragma unroll
        for (int j = 0; j < 8; j++) {
            const int mt = j >> 1, hh = j & 1;
            const int rcl = scls[mtB * 128 + wm * 64 + mt * 16 + hh * 8 + (lane >> 2)];
            float tmax = NEGINF;
#pragma unroll
            for (int nt = 0; nt < 4; nt++) {
                float l0 = acc[mt][nt][hh * 2], l1 = acc[mt][nt][hh * 2 + 1];
                if (ccls[nt * 2] != rcl)     { mn_[j] = fminf(mn_[j], l0); tmax = fmaxf(tmax, l0); }
                if (ccls[nt * 2 + 1] != rcl) { mn_[j] = fminf(mn_[j], l1); tmax = fmaxf(tmax, l1); }
            }
            if (tmax != NEGINF) {
                float nm = fmaxf(m_[j], tmax * CQ);
                float a0 = 0.f, a1 = 0.f;
#pragma unroll
                for (int nt = 0; nt < 4; nt++) {
                    float l0 = acc[mt][nt][hh * 2], l1 = acc[mt][nt][hh * 2 + 1];
                    a0 += ex2f((ccls[nt * 2] != rcl)     ? l0 * CQ - nm : NEGINF);
                    a1 += ex2f((ccls[nt * 2 + 1] != rcl) ? l1 * CQ - nm : NEGINF);
                }
                s_[j] = s_[j] * ex2f(m_[j] - nm) + a0 + a1;
                m_[j] = nm;
            }
        }
    };

#pragma unroll 1
    for (int i = 0; i < 128; i++) {
        if (i == 127) { CP_WAIT0(); } else { CP_WAIT1(); }
        __syncthreads();
        if (i < 126) { loadB(i + 2, (i + 2) % 3); CP_COMMIT(); }

        const int kc = i & 7, ct = i >> 3;
        const uint32_t Bst = sb + SM_B + (uint32_t)(i % 3) * 32768u;
        if (kc == 0) {
#pragma unroll
            for (int mt = 0; mt < 4; mt++)
#pragma unroll
                for (int nt = 0; nt < 4; nt++)
#pragma unroll
                    for (int j = 0; j < 4; j++) acc[mt][nt][j] = 0.f;
        }

#pragma unroll
        for (int ks = 0; ks < 2; ks++) {
            uint32_t bh[2][4], bl[2][4];
            const uint32_t cx = (uint32_t)(((ks * 2 + bKg) ^ fnB) & 3) << 4;
#pragma unroll
            for (int p = 0; p < 2; p++) {
                uint32_t base = Bst + bOff + (uint32_t)p * 1024u + cx;
                ldsm4(bh[p], base);
                ldsm4(bl[p], base + 16384u);
            }
            const uint32_t ach = (uint32_t)(kc * 4 + ks * 2 + aKg);
#pragma unroll
            for (int mt = 0; mt < 4; mt++) {
                uint32_t ah[4];
                ldsm4(ah, aOff + (uint32_t)mt * 8192u + ((ach ^ (uint32_t)a7s) << 4));
#pragma unroll
                for (int p = 0; p < 2; p++)
#pragma unroll
                    for (int hh = 0; hh < 2; hh++) {
                        int nt = p * 2 + hh;
                        mma_h(acc[mt][nt], ah, &bh[p][hh * 2]);
                        mma_h(acc[mt][nt], ah, &bl[p][hh * 2]);
                    }
            }
        }

        if (kc == 7) epilogue(ct);
    }

    /* ---- merge across the 4 lanes sharing each row (lane bits 0,1) ---- */
#pragma unroll
    for (int j = 0; j < 8; j++) {
#pragma unroll
        for (int d = 1; d <= 2; d <<= 1) {
            float om = __shfl_xor_sync(0xFFFFFFFFu, m_[j], d);
            float os = __shfl_xor_sync(0xFFFFFFFFu, s_[j], d);
            float on = __shfl_xor_sync(0xFFFFFFFFu, mn_[j], d);
            float nm = fmaxf(m_[j], om);
            float t0 = (m_[j] == NEGINF) ? 0.f : s_[j] * ex2f(m_[j] - nm);
            float t1 = (om == NEGINF) ? 0.f : os * ex2f(om - nm);
            s_[j] = t0 + t1; m_[j] = nm; mn_[j] = fminf(mn_[j], on);
        }
    }

    /* ---- cross-warp (wn 0..7) merge via SMEM (reuse B region) ---- */
    __syncthreads();
    float* mgM = (float*)(smem + SM_B);        /* [8][128] */
    float* mgS = mgM + 1024;
    float* mgN = mgS + 1024;
    if ((lane & 3) == 0) {
#pragma unroll
        for (int j = 0; j < 8; j++) {
            int row = wm * 64 + (j >> 1) * 16 + (j & 1) * 8 + (lane >> 2);
            mgM[wn * 128 + row] = m_[j];
            mgS[wn * 128 + row] = s_[j];
            mgN[wn * 128 + row] = mn_[j];
        }
    }
    __syncthreads();
    if (tid < 128) {
        float M = NEGINF, S = 0.f, MN = POSINF;
#pragma unroll
        for (int t = 0; t < 8; t++) M = fmaxf(M, mgM[t * 128 + tid]);
        if (M != NEGINF) {
#pragma unroll
            for (int t = 0; t < 8; t++) {
                float mt_ = mgM[t * 128 + tid];
                if (mt_ != NEGINF) S += mgS[t * 128 + tid] * ex2f(mt_ - M);
            }
        }
#pragma unroll
        for (int t = 0; t < 8; t++) MN = fminf(MN, mgN[t * 128 + tid]);
        g_m[R0 + tid] = M;
        g_s[R0 + tid] = S;
        /* per-chunk class histogram + class-min */
        int c = scls[mtB * 128 + tid];
        atomicAdd(&sh_h[c], 1);
        atomicMin(&sh_mk[c], fkey(MN));
    }
    __syncthreads();
    if (tid < NC) {
        g_hist [b][mtB][tid] = sh_h[tid];
        g_chmin[b][mtB][tid] = sh_mk[tid];
    }
}

/* ================= Kernel 2: final 3-way LSE + stable class-sorted scatter === */
__global__ void nce_final(const float* __restrict__ src, const float* __restrict__ tgt,
                          const int* __restrict__ cls, float* __restrict__ out)
{
    const int ch = blockIdx.x, b = blockIdx.y, tid = threadIdx.x;
    const int lane = tid & 31, w = tid >> 5;
    const int row = b * NP + ch * 128 + tid;
    const float NEGINF = __int_as_float(0xff800000);

    __shared__ int      hist_s[32][NC];
    __shared__ unsigned chm_s [32][NC];
    __shared__ int      pref_s[NC];
    __shared__ int      cnt_s [NC];
    __shared__ float    small_s[NC];
    __shared__ int      wcnt[4][NC];

    for (int i = tid; i < 32 * NC; i += 128) {
        ((int*)hist_s)[i]     = ((const int*)g_hist [b])[i];
        ((unsigned*)chm_s)[i] = ((const unsigned*)g_chmin[b])[i];
    }
    __syncthreads();
    if (tid < NC) {
        int run = 0, mypref = 0;
        unsigned mn = 0xFF800000u;
        for (int h2 = 0; h2 < 32; h2++) {
            if (h2 == ch) mypref = run;
            run += hist_s[h2][tid];
            mn = min(mn, chm_s[h2][tid]);
        }
        pref_s[tid] = mypref;
        cnt_s[tid] = run;
        small_s[tid] = fminf(funkey(mn), -10.0f) * INV_T;
    }

    const int c = cls[row];
    unsigned match = __match_any_sync(0xFFFFFFFFu, c);
    int lr = __popc(match & ((1u << lane) - 1u));
#pragma unroll
    for (int c2 = 0; c2 < NC; c2++) {
        unsigned bal = __ballot_sync(0xFFFFFFFFu, c == c2);
        if (lane == c2) wcnt[w][c2] = __popc(bal);
    }
    __syncthreads();
    for (int w2 = 0; w2 < w; w2++) lr += wcnt[w2][c];
    int classpref = 0;
    for (int c2 = 0; c2 < c; c2++) classpref += cnt_s[c2];
    const int opos = b * NP + classpref + pref_s[c] + lr;

    const float4* s4 = (const float4*)(src + (size_t)row * DIM);
    const float4* t4 = (const float4*)(tgt + (size_t)row * DIM);
    float p0 = 0.f, p1 = 0.f, p2 = 0.f, p3 = 0.f;
#pragma unroll
    for (int d = 0; d < 64; d++) {
        float4 a = s4[d], v = t4[d];
        p0 += a.x * v.x; p1 += a.y * v.y; p2 += a.z * v.z; p3 += a.w * v.w;
    }
    const float pos_n = (p0 + p1 + p2 + p3) * INV_T;

    const float M = g_m[row], S = g_s[row];
    const float lneg = (S > 0.f) ? (M * LN2F + logf(S)) : NEGINF;

    const int   npad = cnt_s[c] - 1;
    const float pad  = (npad > 0) ? (logf((float)npad) + small_s[c]) : NEGINF;

    const float Mx  = fmaxf(pos_n, fmaxf(lneg, pad));
    const float sum = expf(pos_n - Mx) + expf(lneg - Mx) + expf(pad - Mx);
    out[opos] = Mx + logf(sum) - pos_n;
}

/* ============================================================================ */
extern "C" void kernel_launch(void* const* d_in, const int* in_sizes, int n_in,
                              void* d_out, int out_size)
{
    const float* src = (const float*)d_in[0];
    const float* tgt = (const float*)d_in[1];
    const int*   cls = (const int*)d_in[2];
    float*       out = (float*)d_out;

    cudaFuncSetAttribute(nce_gemm_mma, cudaFuncAttributeMaxDynamicSharedMemorySize, SMEM_BYTES);

    cvt_split<<<NROWS * DIM / 4 / 256, 256>>>(tgt);
    nce_gemm_mma<<<dim3(32, NBATCH), 512, SMEM_BYTES>>>(src, cls);
    nce_final<<<dim3(32, NBATCH), 128>>>(src, tgt, cls, out);
}

// round 10
// speedup vs baseline: 9.6937x; 1.6604x over previous
#include <cuda_runtime.h>
#include <cuda_fp16.h>
#include <cstdint>

#define NBATCH 4
#define NP     4096
#define DIM    256
#define NC     5
#define NROWS  (NBATCH * NP)

#define INV_T  14.285714285714286f            /* 1/0.07 */
#define CQ     20.60992915555662f             /* log2(e)/0.07 */
#define LN2F   0.6931471805599453f

/* ---- SMEM layout (bytes) ---- */
#define SM_A     0          /* Ah: 128 rows x 512B, swizzled (64 KB) */
#define SM_B     65536      /* 3 stages x 32768 (stage = 256 rows x 128B, hi only) */
#define SM_CLS   163840     /* 4096 ints */
#define SMEM_BYTES 180224

/* ---- persistent scratch (no allocations allowed) ---- */
__device__ uint32_t g_Bh[NROWS * DIM / 2];   /* tgt hi (fp16x2-packed) */
__device__ float g_m [NROWS];
__device__ float g_s [NROWS];
__device__ int      g_hist [NBATCH][32][NC];
__device__ unsigned g_chmin[NBATCH][32][NC];

/* ================= helpers ================= */
__device__ __forceinline__ uint32_t smem_u32(const void* p) {
    uint32_t a;
    asm("{ .reg .u64 t; cvta.to.shared.u64 t, %1; cvt.u32.u64 %0, t; }" : "=r"(a) : "l"(p));
    return a;
}
__device__ __forceinline__ float ex2f(float x) {
    float y; asm("ex2.approx.ftz.f32 %0, %1;" : "=f"(y) : "f"(x)); return y;
}
__device__ __forceinline__ void cp16(uint32_t dst, const void* src) {
    asm volatile("cp.async.cg.shared.global [%0], [%1], 16;" :: "r"(dst), "l"(src));
}
#define CP_COMMIT() asm volatile("cp.async.commit_group;" ::: "memory")
#define CP_WAIT1()  asm volatile("cp.async.wait_group 1;" ::: "memory")
#define CP_WAIT0()  asm volatile("cp.async.wait_group 0;" ::: "memory")

__device__ __forceinline__ void ldsm4(uint32_t (&r)[4], uint32_t addr) {
    asm volatile("ldmatrix.sync.aligned.m8n8.x4.shared.b16 {%0,%1,%2,%3}, [%4];"
                 : "=r"(r[0]), "=r"(r[1]), "=r"(r[2]), "=r"(r[3]) : "r"(addr));
}
__device__ __forceinline__ void mma_h(float (&d)[4], const uint32_t* a, const uint32_t* b) {
    asm volatile("mma.sync.aligned.m16n8k16.row.col.f32.f16.f16.f32 "
                 "{%0,%1,%2,%3}, {%4,%5,%6,%7}, {%8,%9}, {%0,%1,%2,%3};"
                 : "+f"(d[0]), "+f"(d[1]), "+f"(d[2]), "+f"(d[3])
                 : "r"(a[0]), "r"(a[1]), "r"(a[2]), "r"(a[3]), "r"(b[0]), "r"(b[1]));
}
__device__ __forceinline__ uint32_t pkh(__half a, __half b) {
    return (uint32_t)__half_as_ushort(a) | ((uint32_t)__half_as_ushort(b) << 16);
}
__device__ __forceinline__ unsigned fkey(float x) {
    unsigned u = __float_as_uint(x);
    return (u & 0x80000000u) ? ~u : (u | 0x80000000u);
}
__device__ __forceinline__ float funkey(unsigned k) {
    unsigned u = (k & 0x80000000u) ? (k & 0x7FFFFFFFu) : ~k;
    return __uint_as_float(u);
}

/* ================= Kernel 0: tgt fp32 -> fp16 hi ================= */
__global__ __launch_bounds__(256)
void cvt_split(const float* __restrict__ tgt)
{
    int i = blockIdx.x * 256 + threadIdx.x;        /* float4 index */
    float4 v = ((const float4*)tgt)[i];
    ((uint2*)g_Bh)[i] = make_uint2(
        pkh(__float2half_rn(v.x), __float2half_rn(v.y)),
        pkh(__float2half_rn(v.z), __float2half_rn(v.w)));
}

/* ================= Kernel 1: fp16 single-term mma GEMM + fused masked softmax =
   grid (32 M-tiles, 4 batches), 512 threads = 16 warps as 2(M) x 8(N).
   Warp tile 64x32. CTA N-tile 256 cols. A converted fp32->fp16 in prologue,
   resident in SMEM. B hi streamed in 64-k stages (128B rows), 3-ring.
   Emits per-chunk class histogram + class-min.                                */
__global__ __launch_bounds__(512, 1)
void nce_gemm_mma(const float* __restrict__ src, const int* __restrict__ cls)
{
    extern __shared__ __align__(1024) char smem[];
    const uint32_t sb = smem_u32(smem);
    const int tid = threadIdx.x, lane = tid & 31, w = tid >> 5;
    const int wm = w >> 3, wn = w & 7;
    const int b = blockIdx.y, mtB = blockIdx.x;
    const int R0 = b * NP + mtB * 128;
    const float NEGINF = __int_as_float(0xff800000);
    const float POSINF = __int_as_float(0x7f800000);
    int* scls = (int*)(smem + SM_CLS);

    __shared__ int      sh_h[NC];
    __shared__ unsigned sh_mk[NC];
    if (tid < NC) { sh_h[tid] = 0; sh_mk[tid] = 0xFF800000u; /* fkey(+inf) */ }

    /* ---- B stage loader: tile i = (ct=i>>2 [256 rows], kc=i&3 [64 k]) ----
       stage row = 128 B (64 fp16), 8 chunks of 16B, swizzle chunk^(row&7).   */
    auto loadB = [&](int i, int stage) {
        const int ct = i >> 2, kc = i & 3;
        const uint32_t* __restrict__ gh = g_Bh + (size_t)(b * NP + ct * 256) * 128 + kc * 32;
        const uint32_t dbase = sb + SM_B + (uint32_t)stage * 32768u;
#pragma unroll
        for (int q = 0; q < 4; q++) {
            int idx = tid + q * 512;                 /* 0..2047 */
            int n = idx >> 3, c = idx & 7;
            uint32_t dst = dbase + (uint32_t)n * 128u + (uint32_t)((c ^ (n & 7)) << 4);
            cp16(dst, gh + (size_t)n * 128 + c * 4);
        }
    };
    loadB(0, 0); CP_COMMIT();
    loadB(1, 1); CP_COMMIT();

    /* ---- A prologue: fp32 rows -> fp16, swizzled STS (row*512 + (c^row&7)*16) */
    {
        const float4* Ag = (const float4*)(src + (size_t)R0 * DIM);
#pragma unroll
        for (int q = 0; q < 8; q++) {
            int line = tid + q * 512;               /* 0..4095 */
            int row = line >> 5, c = line & 31;
            float4 v0 = Ag[row * 64 + c * 2];
            float4 v1 = Ag[row * 64 + c * 2 + 1];
            uint4 h = make_uint4(pkh(__float2half_rn(v0.x), __float2half_rn(v0.y)),
                                 pkh(__float2half_rn(v0.z), __float2half_rn(v0.w)),
                                 pkh(__float2half_rn(v1.x), __float2half_rn(v1.y)),
                                 pkh(__float2half_rn(v1.z), __float2half_rn(v1.w)));
            *(uint4*)(smem + SM_A + row * 512 + ((c ^ (row & 7)) << 4)) = h;
        }
    }

    /* ---- class table ---- */
#pragma unroll
    for (int q = 0; q < 2; q++)
        ((int4*)scls)[tid + q * 512] = ((const int4*)(cls + b * NP))[tid + q * 512];

    /* ---- per-lane constants ---- */
    const int la7 = lane & 7;
    const int aRowBase = wm * 64 + ((lane >> 3) & 1) * 8 + la7;    /* + mt*16 */
    const uint32_t aOff = sb + SM_A + (uint32_t)aRowBase * 512u;
    const int a7s = aRowBase & 7;
    const int aKg = lane >> 4;                                     /* k8 group */
    const int nB = wn * 32 + ((lane >> 4) & 1) * 8 + la7;          /* + p*16 */
    const uint32_t bOff = (uint32_t)nB * 128u;
    const int b7s = nB & 7;
    const int bKg = (lane >> 3) & 1;

    float m_[8], s_[8], mn_[8];
#pragma unroll
    for (int j = 0; j < 8; j++) { m_[j] = NEGINF; s_[j] = 0.f; mn_[j] = POSINF; }

    float acc[4][4][4];

    /* ---- epilogue: masked online update over this 256-col tile ---- */
    auto epilogue = [&](int ct) {
        const int cb = ct * 256 + wn * 32 + (lane & 3) * 2;
        int ccls[8];
#pragma unroll
        for (int nt = 0; nt < 4; nt++) {
            ccls[nt * 2]     = scls[cb + nt * 8];
            ccls[nt * 2 + 1] = scls[cb + nt * 8 + 1];
        }
#pragma unroll
        for (int j = 0; j < 8; j++) {
            const int mt = j >> 1, hh = j & 1;
            const int rcl = scls[mtB * 128 + wm * 64 + mt * 16 + hh * 8 + (lane >> 2)];
            float tmax = NEGINF;
#pragma unroll
            for (int nt = 0; nt < 4; nt++) {
                float l0 = acc[mt][nt][hh * 2], l1 = acc[mt][nt][hh * 2 + 1];
                if (ccls[nt * 2] != rcl)     { mn_[j] = fminf(mn_[j], l0); tmax = fmaxf(tmax, l0); }
                if (ccls[nt * 2 + 1] != rcl) { mn_[j] = fminf(mn_[j], l1); tmax = fmaxf(tmax, l1); }
            }
            if (tmax != NEGINF) {
                float nm = fmaxf(m_[j], tmax * CQ);
                float a0 = 0.f, a1 = 0.f;
#pragma unroll
                for (int nt = 0; nt < 4; nt++) {
                    float l0 = acc[mt][nt][hh * 2], l1 = acc[mt][nt][hh * 2 + 1];
                    a0 += ex2f((ccls[nt * 2] != rcl)     ? l0 * CQ - nm : NEGINF);
                    a1 += ex2f((ccls[nt * 2 + 1] != rcl) ? l1 * CQ - nm : NEGINF);
                }
                s_[j] = s_[j] * ex2f(m_[j] - nm) + a0 + a1;
                m_[j] = nm;
            }
        }
    };

#pragma unroll 1
    for (int i = 0; i < 64; i++) {
        if (i == 63) { CP_WAIT0(); } else { CP_WAIT1(); }
        __syncthreads();
        if (i < 62) { loadB(i + 2, (i + 2) % 3); CP_COMMIT(); }

        const int kc = i & 3, ct = i >> 2;
        const uint32_t Bst = sb + SM_B + (uint32_t)(i % 3) * 32768u;
        if (kc == 0) {
#pragma unroll
            for (int mt = 0; mt < 4; mt++)
#pragma unroll
                for (int nt = 0; nt < 4; nt++)
#pragma unroll
                    for (int j = 0; j < 4; j++) acc[mt][nt][j] = 0.f;
        }

#pragma unroll
        for (int ks = 0; ks < 4; ks++) {
            uint32_t bh[2][4];
            const uint32_t cb = (uint32_t)((ks * 2 + bKg) ^ b7s) << 4;
#pragma unroll
            for (int p = 0; p < 2; p++)
                ldsm4(bh[p], Bst + bOff + (uint32_t)p * 2048u + cb);
            const uint32_t ach = (uint32_t)(kc * 8 + ks * 2 + aKg);
#pragma unroll
            for (int mt = 0; mt < 4; mt++) {
                uint32_t ah[4];
                ldsm4(ah, aOff + (uint32_t)mt * 8192u + ((ach ^ (uint32_t)a7s) << 4));
#pragma unroll
                for (int p = 0; p < 2; p++)
#pragma unroll
                    for (int hh = 0; hh < 2; hh++)
                        mma_h(acc[mt][p * 2 + hh], ah, &bh[p][hh * 2]);
            }
        }

        if (kc == 3) epilogue(ct);
    }

    /* ---- merge across the 4 lanes sharing each row (lane bits 0,1) ---- */
#pragma unroll
    for (int j = 0; j < 8; j++) {
#pragma unroll
        for (int d = 1; d <= 2; d <<= 1) {
            float om = __shfl_xor_sync(0xFFFFFFFFu, m_[j], d);
            float os = __shfl_xor_sync(0xFFFFFFFFu, s_[j], d);
            float on = __shfl_xor_sync(0xFFFFFFFFu, mn_[j], d);
            float nm = fmaxf(m_[j], om);
            float t0 = (m_[j] == NEGINF) ? 0.f : s_[j] * ex2f(m_[j] - nm);
            float t1 = (om == NEGINF) ? 0.f : os * ex2f(om - nm);
            s_[j] = t0 + t1; m_[j] = nm; mn_[j] = fminf(mn_[j], on);
        }
    }

    /* ---- cross-warp (wn 0..7) merge via SMEM (reuse B region) ---- */
    __syncthreads();
    float* mgM = (float*)(smem + SM_B);        /* [8][128] */
    float* mgS = mgM + 1024;
    float* mgN = mgS + 1024;
    if ((lane & 3) == 0) {
#pragma unroll
        for (int j = 0; j < 8; j++) {
            int row = wm * 64 + (j >> 1) * 16 + (j & 1) * 8 + (lane >> 2);
            mgM[wn * 128 + row] = m_[j];
            mgS[wn * 128 + row] = s_[j];
            mgN[wn * 128 + row] = mn_[j];
        }
    }
    __syncthreads();
    if (tid < 128) {
        float M = NEGINF, S = 0.f, MN = POSINF;
#pragma unroll
        for (int t = 0; t < 8; t++) M = fmaxf(M, mgM[t * 128 + tid]);
        if (M != NEGINF) {
#pragma unroll
            for (int t = 0; t < 8; t++) {
                float mt_ = mgM[t * 128 + tid];
                if (mt_ != NEGINF) S += mgS[t * 128 + tid] * ex2f(mt_ - M);
            }
        }
#pragma unroll
        for (int t = 0; t < 8; t++) MN = fminf(MN, mgN[t * 128 + tid]);
        g_m[R0 + tid] = M;
        g_s[R0 + tid] = S;
        /* per-chunk class histogram + class-min */
        int c = scls[mtB * 128 + tid];
        atomicAdd(&sh_h[c], 1);
        atomicMin(&sh_mk[c], fkey(MN));
    }
    __syncthreads();
    if (tid < NC) {
        g_hist [b][mtB][tid] = sh_h[tid];
        g_chmin[b][mtB][tid] = sh_mk[tid];
    }
}

/* ================= Kernel 2: final 3-way LSE + stable class-sorted scatter === */
__global__ void nce_final(const float* __restrict__ src, const float* __restrict__ tgt,
                          const int* __restrict__ cls, float* __restrict__ out)
{
    const int ch = blockIdx.x, b = blockIdx.y, tid = threadIdx.x;
    const int lane = tid & 31, w = tid >> 5;
    const int row = b * NP + ch * 128 + tid;
    const float NEGINF = __int_as_float(0xff800000);

    __shared__ int      hist_s[32][NC];
    __shared__ unsigned chm_s [32][NC];
    __shared__ int      pref_s[NC];
    __shared__ int      cnt_s [NC];
    __shared__ float    small_s[NC];
    __shared__ int      wcnt[4][NC];

    for (int i = tid; i < 32 * NC; i += 128) {
        ((int*)hist_s)[i]     = ((const int*)g_hist [b])[i];
        ((unsigned*)chm_s)[i] = ((const unsigned*)g_chmin[b])[i];
    }
    __syncthreads();
    if (tid < NC) {
        int run = 0, mypref = 0;
        unsigned mn = 0xFF800000u;
        for (int h2 = 0; h2 < 32; h2++) {
            if (h2 == ch) mypref = run;
            run += hist_s[h2][tid];
            mn = min(mn, chm_s[h2][tid]);
        }
        pref_s[tid] = mypref;
        cnt_s[tid] = run;
        small_s[tid] = fminf(funkey(mn), -10.0f) * INV_T;
    }

    const int c = cls[row];
    unsigned match = __match_any_sync(0xFFFFFFFFu, c);
    int lr = __popc(match & ((1u << lane) - 1u));
#pragma unroll
    for (int c2 = 0; c2 < NC; c2++) {
        unsigned bal = __ballot_sync(0xFFFFFFFFu, c == c2);
        if (lane == c2) wcnt[w][c2] = __popc(bal);
    }
    __syncthreads();
    for (int w2 = 0; w2 < w; w2++) lr += wcnt[w2][c];
    int classpref = 0;
    for (int c2 = 0; c2 < c; c2++) classpref += cnt_s[c2];
    const int opos = b * NP + classpref + pref_s[c] + lr;

    const float4* s4 = (const float4*)(src + (size_t)row * DIM);
    const float4* t4 = (const float4*)(tgt + (size_t)row * DIM);
    float p0 = 0.f, p1 = 0.f, p2 = 0.f, p3 = 0.f;
#pragma unroll
    for (int d = 0; d < 64; d++) {
        float4 a = s4[d], v = t4[d];
        p0 += a.x * v.x; p1 += a.y * v.y; p2 += a.z * v.z; p3 += a.w * v.w;
    }
    const float pos_n = (p0 + p1 + p2 + p3) * INV_T;

    const float M = g_m[row], S = g_s[row];
    const float lneg = (S > 0.f) ? (M * LN2F + logf(S)) : NEGINF;

    const int   npad = cnt_s[c] - 1;
    const float pad  = (npad > 0) ? (logf((float)npad) + small_s[c]) : NEGINF;

    const float Mx  = fmaxf(pos_n, fmaxf(lneg, pad));
    const float sum = expf(pos_n - Mx) + expf(lneg - Mx) + expf(pad - Mx);
    out[opos] = Mx + logf(sum) - pos_n;
}

/* ============================================================================ */
extern "C" void kernel_launch(void* const* d_in, const int* in_sizes, int n_in,
                              void* d_out, int out_size)
{
    const float* src = (const float*)d_in[0];
    const float* tgt = (const float*)d_in[1];
    const int*   cls = (const int*)d_in[2];
    float*       out = (float*)d_out;

    cudaFuncSetAttribute(nce_gemm_mma, cudaFuncAttributeMaxDynamicSharedMemorySize, SMEM_BYTES);

    cvt_split<<<NROWS * DIM / 4 / 256, 256>>>(tgt);
    nce_gemm_mma<<<dim3(32, NBATCH), 512, SMEM_BYTES>>>(src, cls);
    nce_final<<<dim3(32, NBATCH), 128>>>(src, tgt, cls, out);
}

// round 11
// speedup vs baseline: 10.1947x; 1.0517x over previous
#include <cuda_runtime.h>
#include <cuda_fp16.h>
#include <cstdint>

#define NBATCH 4
#define NP     4096
#define DIM    256
#define NC     5
#define NROWS  (NBATCH * NP)

#define INV_T  14.285714285714286f            /* 1/0.07 */
#define CQ     20.60992915555662f             /* log2(e)/0.07 */
#define LN2F   0.6931471805599453f

/* ---- SMEM layout (bytes) ---- */
#define SM_A     0          /* Ah: 128 rows x 512B, swizzled (64 KB) */
#define SM_B     65536      /* 4 stages x 32768 (stage = 256 rows x 128B, hi only) */
#define SM_CLS   196608     /* 4096 ints */
#define SMEM_BYTES 212992

/* ---- persistent scratch (no allocations allowed) ---- */
__device__ uint32_t g_Bh[NROWS * DIM / 2];   /* tgt hi (fp16x2-packed) */
__device__ float g_m [NROWS];
__device__ float g_s [NROWS];
__device__ int      g_hist [NBATCH][32][NC];
__device__ unsigned g_chmin[NBATCH][32][NC];

/* ================= helpers ================= */
__device__ __forceinline__ uint32_t smem_u32(const void* p) {
    uint32_t a;
    asm("{ .reg .u64 t; cvta.to.shared.u64 t, %1; cvt.u32.u64 %0, t; }" : "=r"(a) : "l"(p));
    return a;
}
__device__ __forceinline__ float ex2f(float x) {
    float y; asm("ex2.approx.ftz.f32 %0, %1;" : "=f"(y) : "f"(x)); return y;
}
__device__ __forceinline__ void cp16(uint32_t dst, const void* src) {
    asm volatile("cp.async.cg.shared.global [%0], [%1], 16;" :: "r"(dst), "l"(src));
}
#define CP_COMMIT() asm volatile("cp.async.commit_group;" ::: "memory")
#define CP_WAIT0()  asm volatile("cp.async.wait_group 0;" ::: "memory")

__device__ __forceinline__ void ldsm4(uint32_t (&r)[4], uint32_t addr) {
    asm volatile("ldmatrix.sync.aligned.m8n8.x4.shared.b16 {%0,%1,%2,%3}, [%4];"
                 : "=r"(r[0]), "=r"(r[1]), "=r"(r[2]), "=r"(r[3]) : "r"(addr));
}
__device__ __forceinline__ void mma_h(float (&d)[4], const uint32_t* a, const uint32_t* b) {
    asm volatile("mma.sync.aligned.m16n8k16.row.col.f32.f16.f16.f32 "
                 "{%0,%1,%2,%3}, {%4,%5,%6,%7}, {%8,%9}, {%0,%1,%2,%3};"
                 : "+f"(d[0]), "+f"(d[1]), "+f"(d[2]), "+f"(d[3])
                 : "r"(a[0]), "r"(a[1]), "r"(a[2]), "r"(a[3]), "r"(b[0]), "r"(b[1]));
}
__device__ __forceinline__ uint32_t pkh(__half a, __half b) {
    return (uint32_t)__half_as_ushort(a) | ((uint32_t)__half_as_ushort(b) << 16);
}
__device__ __forceinline__ unsigned fkey(float x) {
    unsigned u = __float_as_uint(x);
    return (u & 0x80000000u) ? ~u : (u | 0x80000000u);
}
__device__ __forceinline__ float funkey(unsigned k) {
    unsigned u = (k & 0x80000000u) ? (k & 0x7FFFFFFFu) : ~k;
    return __uint_as_float(u);
}

/* ================= Kernel 0: tgt fp32 -> fp16 hi ================= */
__global__ __launch_bounds__(256)
void cvt_split(const float* __restrict__ tgt)
{
    int i = blockIdx.x * 256 + threadIdx.x;        /* float4 index */
    float4 v = ((const float4*)tgt)[i];
    ((uint2*)g_Bh)[i] = make_uint2(
        pkh(__float2half_rn(v.x), __float2half_rn(v.y)),
        pkh(__float2half_rn(v.z), __float2half_rn(v.w)));
}

/* ================= Kernel 1: fp16 mma GEMM + fused masked softmax =============
   grid (32 M-tiles, 4 batches), 512 threads = 16 warps as 2(M) x 8(N).
   Warp tile 64x32. A fp32->fp16 in prologue, resident. B hi streamed in 64-k
   stages (128B rows), 4-slot ring, barrier only every 2nd iteration so the
   per-tile epilogue (MUFU/ALU) of lagging warps overlaps MMA of leading warps.
   Emits per-chunk class histogram + class-min.                                */
__global__ __launch_bounds__(512, 1)
void nce_gemm_mma(const float* __restrict__ src, const int* __restrict__ cls)
{
    extern __shared__ __align__(1024) char smem[];
    const uint32_t sb = smem_u32(smem);
    const int tid = threadIdx.x, lane = tid & 31, w = tid >> 5;
    const int wm = w >> 3, wn = w & 7;
    const int b = blockIdx.y, mtB = blockIdx.x;
    const int R0 = b * NP + mtB * 128;
    const float NEGINF = __int_as_float(0xff800000);
    const float POSINF = __int_as_float(0x7f800000);
    int* scls = (int*)(smem + SM_CLS);

    __shared__ int      sh_h[NC];
    __shared__ unsigned sh_mk[NC];
    if (tid < NC) { sh_h[tid] = 0; sh_mk[tid] = 0xFF800000u; /* fkey(+inf) */ }

    /* ---- B stage loader: tile i = (ct=i>>2 [256 rows], kc=i&3 [64 k]) ----
       stage row = 128 B (64 fp16), 8 chunks of 16B, swizzle chunk^(row&7).   */
    auto loadB = [&](int i) {
        const int ct = i >> 2, kc = i & 3, stage = i & 3;
        const uint32_t* __restrict__ gh = g_Bh + (size_t)(b * NP + ct * 256) * 128 + kc * 32;
        const uint32_t dbase = sb + SM_B + (uint32_t)stage * 32768u;
#pragma unroll
        for (int q = 0; q < 4; q++) {
            int idx = tid + q * 512;                 /* 0..2047 */
            int n = idx >> 3, c = idx & 7;
            uint32_t dst = dbase + (uint32_t)n * 128u + (uint32_t)((c ^ (n & 7)) << 4);
            cp16(dst, gh + (size_t)n * 128 + c * 4);
        }
    };
    loadB(0); CP_COMMIT();
    loadB(1); CP_COMMIT();

    /* ---- A prologue: fp32 rows -> fp16, swizzled STS (row*512 + (c^row&7)*16) */
    {
        const float4* Ag = (const float4*)(src + (size_t)R0 * DIM);
#pragma unroll
        for (int q = 0; q < 8; q++) {
            int line = tid + q * 512;               /* 0..4095 */
            int row = line >> 5, c = line & 31;
            float4 v0 = Ag[row * 64 + c * 2];
            float4 v1 = Ag[row * 64 + c * 2 + 1];
            uint4 h = make_uint4(pkh(__float2half_rn(v0.x), __float2half_rn(v0.y)),
                                 pkh(__float2half_rn(v0.z), __float2half_rn(v0.w)),
                                 pkh(__float2half_rn(v1.x), __float2half_rn(v1.y)),
                                 pkh(__float2half_rn(v1.z), __float2half_rn(v1.w)));
            *(uint4*)(smem + SM_A + row * 512 + ((c ^ (row & 7)) << 4)) = h;
        }
    }

    /* ---- class table ---- */
#pragma unroll
    for (int q = 0; q < 2; q++)
        ((int4*)scls)[tid + q * 512] = ((const int4*)(cls + b * NP))[tid + q * 512];

    /* ---- per-lane constants ---- */
    const int la7 = lane & 7;
    const int aRowBase = wm * 64 + ((lane >> 3) & 1) * 8 + la7;    /* + mt*16 */
    const uint32_t aOff = sb + SM_A + (uint32_t)aRowBase * 512u;
    const int a7s = aRowBase & 7;
    const int aKg = lane >> 4;                                     /* k8 group */
    const int nB = wn * 32 + ((lane >> 4) & 1) * 8 + la7;          /* + p*16 */
    const uint32_t bOff = (uint32_t)nB * 128u;
    const int b7s = nB & 7;
    const int bKg = (lane >> 3) & 1;

    float m_[8], s_[8], mn_[8];
#pragma unroll
    for (int j = 0; j < 8; j++) { m_[j] = NEGINF; s_[j] = 0.f; mn_[j] = POSINF; }

    float acc[4][4][4];

    /* ---- epilogue: masked online update over this 256-col tile ---- */
    auto epilogue = [&](int ct) {
        const int cb = ct * 256 + wn * 32 + (lane & 3) * 2;
        int ccls[8];
#pragma unroll
        for (int nt = 0; nt < 4; nt++) {
            ccls[nt * 2]     = scls[cb + nt * 8];
            ccls[nt * 2 + 1] = scls[cb + nt * 8 + 1];
        }
#pragma unroll
        for (int j = 0; j < 8; j++) {
            const int mt = j >> 1, hh = j & 1;
            const int rcl = scls[mtB * 128 + wm * 64 + mt * 16 + hh * 8 + (lane >> 2)];
            float tmax = NEGINF;
#pragma unroll
            for (int nt = 0; nt < 4; nt++) {
                float l0 = acc[mt][nt][hh * 2], l1 = acc[mt][nt][hh * 2 + 1];
                if (ccls[nt * 2] != rcl)     { mn_[j] = fminf(mn_[j], l0); tmax = fmaxf(tmax, l0); }
                if (ccls[nt * 2 + 1] != rcl) { mn_[j] = fminf(mn_[j], l1); tmax = fmaxf(tmax, l1); }
            }
            if (tmax != NEGINF) {
                float nm = fmaxf(m_[j], tmax * CQ);
                float a0 = 0.f, a1 = 0.f;
#pragma unroll
                for (int nt = 0; nt < 4; nt++) {
                    float l0 = acc[mt][nt][hh * 2], l1 = acc[mt][nt][hh * 2 + 1];
                    a0 += ex2f((ccls[nt * 2] != rcl)     ? l0 * CQ - nm : NEGINF);
                    a1 += ex2f((ccls[nt * 2 + 1] != rcl) ? l1 * CQ - nm : NEGINF);
                }
                s_[j] = s_[j] * ex2f(m_[j] - nm) + a0 + a1;
                m_[j] = nm;
            }
        }
    };

    /* initial: stages 0,1 complete + visible to all threads */
    CP_WAIT0();
    __syncthreads();

#pragma unroll 1
    for (int i = 0; i < 64; i++) {
        if (i & 1) {                 /* barrier only at odd iterations */
            CP_WAIT0();              /* own groups for stages i, i+1 done */
            __syncthreads();         /* ... and everyone else's, visible */
        }
        if (i < 62) { loadB(i + 2); CP_COMMIT(); }

        const int kc = i & 3, ct = i >> 2;
        const uint32_t Bst = sb + SM_B + (uint32_t)(i & 3) * 32768u;
        if (kc == 0) {
#pragma unroll
            for (int mt = 0; mt < 4; mt++)
#pragma unroll
                for (int nt = 0; nt < 4; nt++)
#pragma unroll
                    for (int j = 0; j < 4; j++) acc[mt][nt][j] = 0.f;
        }

#pragma unroll
        for (int ks = 0; ks < 4; ks++) {
            uint32_t bh[2][4];
            const uint32_t cb = (uint32_t)((ks * 2 + bKg) ^ b7s) << 4;
#pragma unroll
            for (int p = 0; p < 2; p++)
                ldsm4(bh[p], Bst + bOff + (uint32_t)p * 2048u + cb);
            const uint32_t ach = (uint32_t)(kc * 8 + ks * 2 + aKg);
#pragma unroll
            for (int mt = 0; mt < 4; mt++) {
                uint32_t ah[4];
                ldsm4(ah, aOff + (uint32_t)mt * 8192u + ((ach ^ (uint32_t)a7s) << 4));
#pragma unroll
                for (int p = 0; p < 2; p++)
#pragma unroll
                    for (int hh = 0; hh < 2; hh++)
                        mma_h(acc[mt][p * 2 + hh], ah, &bh[p][hh * 2]);
            }
        }

        if (kc == 3) epilogue(ct);   /* odd i; next iteration has no barrier ->
                                        laggards' epilogue overlaps leaders' MMA */
    }

    /* ---- merge across the 4 lanes sharing each row (lane bits 0,1) ---- */
#pragma unroll
    for (int j = 0; j < 8; j++) {
#pragma unroll
        for (int d = 1; d <= 2; d <<= 1) {
            float om = __shfl_xor_sync(0xFFFFFFFFu, m_[j], d);
            float os = __shfl_xor_sync(0xFFFFFFFFu, s_[j], d);
            float on = __shfl_xor_sync(0xFFFFFFFFu, mn_[j], d);
            float nm = fmaxf(m_[j], om);
            float t0 = (m_[j] == NEGINF) ? 0.f : s_[j] * ex2f(m_[j] - nm);
            float t1 = (om == NEGINF) ? 0.f : os * ex2f(om - nm);
            s_[j] = t0 + t1; m_[j] = nm; mn_[j] = fminf(mn_[j], on);
        }
    }

    /* ---- cross-warp (wn 0..7) merge via SMEM (reuse B region) ---- */
    __syncthreads();
    float* mgM = (float*)(smem + SM_B);        /* [8][128] */
    float* mgS = mgM + 1024;
    float* mgN = mgS + 1024;
    if ((lane & 3) == 0) {
#pragma unroll
        for (int j = 0; j < 8; j++) {
            int row = wm * 64 + (j >> 1) * 16 + (j & 1) * 8 + (lane >> 2);
            mgM[wn * 128 + row] = m_[j];
            mgS[wn * 128 + row] = s_[j];
            mgN[wn * 128 + row] = mn_[j];
        }
    }
    __syncthreads();
    if (tid < 128) {
        float M = NEGINF, S = 0.f, MN = POSINF;
#pragma unroll
        for (int t = 0; t < 8; t++) M = fmaxf(M, mgM[t * 128 + tid]);
        if (M != NEGINF) {
#pragma unroll
            for (int t = 0; t < 8; t++) {
                float mt_ = mgM[t * 128 + tid];
                if (mt_ != NEGINF) S += mgS[t * 128 + tid] * ex2f(mt_ - M);
            }
        }
#pragma unroll
        for (int t = 0; t < 8; t++) MN = fminf(MN, mgN[t * 128 + tid]);
        g_m[R0 + tid] = M;
        g_s[R0 + tid] = S;
        /* per-chunk class histogram + class-min */
        int c = scls[mtB * 128 + tid];
        atomicAdd(&sh_h[c], 1);
        atomicMin(&sh_mk[c], fkey(MN));
    }
    __syncthreads();
    if (tid < NC) {
        g_hist [b][mtB][tid] = sh_h[tid];
        g_chmin[b][mtB][tid] = sh_mk[tid];
    }
}

/* ================= Kernel 2: final 3-way LSE + stable class-sorted scatter === */
__global__ void nce_final(const float* __restrict__ src, const float* __restrict__ tgt,
                          const int* __restrict__ cls, float* __restrict__ out)
{
    const int ch = blockIdx.x, b = blockIdx.y, tid = threadIdx.x;
    const int lane = tid & 31, w = tid >> 5;
    const int row = b * NP + ch * 128 + tid;
    const float NEGINF = __int_as_float(0xff800000);

    __shared__ int      hist_s[32][NC];
    __shared__ unsigned chm_s [32][NC];
    __shared__ int      pref_s[NC];
    __shared__ int      cnt_s [NC];
    __shared__ float    small_s[NC];
    __shared__ int      wcnt[4][NC];

    for (int i = tid; i < 32 * NC; i += 128) {
        ((int*)hist_s)[i]     = ((const int*)g_hist [b])[i];
        ((unsigned*)chm_s)[i] = ((const unsigned*)g_chmin[b])[i];
    }
    __syncthreads();
    if (tid < NC) {
        int run = 0, mypref = 0;
        unsigned mn = 0xFF800000u;
        for (int h2 = 0; h2 < 32; h2++) {
            if (h2 == ch) mypref = run;
            run += hist_s[h2][tid];
            mn = min(mn, chm_s[h2][tid]);
        }
        pref_s[tid] = mypref;
        cnt_s[tid] = run;
        small_s[tid] = fminf(funkey(mn), -10.0f) * INV_T;
    }

    const int c = cls[row];
    unsigned match = __match_any_sync(0xFFFFFFFFu, c);
    int lr = __popc(match & ((1u << lane) - 1u));
#pragma unroll
    for (int c2 = 0; c2 < NC; c2++) {
        unsigned bal = __ballot_sync(0xFFFFFFFFu, c == c2);
        if (lane == c2) wcnt[w][c2] = __popc(bal);
    }
    __syncthreads();
    for (int w2 = 0; w2 < w; w2++) lr += wcnt[w2][c];
    int classpref = 0;
    for (int c2 = 0; c2 < c; c2++) classpref += cnt_s[c2];
    const int opos = b * NP + classpref + pref_s[c] + lr;

    const float4* s4 = (const float4*)(src + (size_t)row * DIM);
    const float4* t4 = (const float4*)(tgt + (size_t)row * DIM);
    float p0 = 0.f, p1 = 0.f, p2 = 0.f, p3 = 0.f;
#pragma unroll
    for (int d = 0; d < 64; d++) {
        float4 a = s4[d], v = t4[d];
        p0 += a.x * v.x; p1 += a.y * v.y; p2 += a.z * v.z; p3 += a.w * v.w;
    }
    const float pos_n = (p0 + p1 + p2 + p3) * INV_T;

    const float M = g_m[row], S = g_s[row];
    const float lneg = (S > 0.f) ? (M * LN2F + logf(S)) : NEGINF;

    const int   npad = cnt_s[c] - 1;
    const float pad  = (npad > 0) ? (logf((float)npad) + small_s[c]) : NEGINF;

    const float Mx  = fmaxf(pos_n, fmaxf(lneg, pad));
    const float sum = expf(pos_n - Mx) + expf(lneg - Mx) + expf(pad - Mx);
    out[opos] = Mx + logf(sum) - pos_n;
}

/* ============================================================================ */
extern "C" void kernel_launch(void* const* d_in, const int* in_sizes, int n_in,
                              void* d_out, int out_size)
{
    const float* src = (const float*)d_in[0];
    const float* tgt = (const float*)d_in[1];
    const int*   cls = (const int*)d_in[2];
    float*       out = (float*)d_out;

    cudaFuncSetAttribute(nce_gemm_mma, cudaFuncAttributeMaxDynamicSharedMemorySize, SMEM_BYTES);

    cvt_split<<<NROWS * DIM / 4 / 256, 256>>>(tgt);
    nce_gemm_mma<<<dim3(32, NBATCH), 512, SMEM_BYTES>>>(src, cls);
    nce_final<<<dim3(32, NBATCH), 128>>>(src, tgt, cls, out);
}

// round 13
// speedup vs baseline: 10.9965x; 1.0786x over previous
#include <cuda_runtime.h>
#include <cuda_fp16.h>
#include <cstdint>

#define NBATCH 4
#define NP     4096
#define DIM    256
#define NC     5
#define NROWS  (NBATCH * NP)

#define INV_T  14.285714285714286f            /* 1/0.07 */
#define CQ     20.60992915555662f             /* log2(e)/0.07 */
#define LN2F   0.6931471805599453f

/* ---- SMEM layout (bytes) ---- */
#define SM_A     0          /* Ah: 128 rows x 512B, swizzled (64 KB) */
#define SM_B     65536      /* per-half: 4 stages x 16384 (stage = 128 rows x 128B); half1 at +65536 */
#define SM_CLS   196608     /* 4096 ints */
#define SMEM_BYTES 212992

/* ---- persistent scratch (no allocations allowed) ---- */
__device__ uint32_t g_Bh[NROWS * DIM / 2];   /* tgt hi (fp16x2-packed) */
__device__ float g_pos[NROWS];               /* exact fp32 positive logit / T */
__device__ float g_m [NROWS];
__device__ float g_s [NROWS];
__device__ int      g_hist [NBATCH][32][NC];
__device__ unsigned g_chmin[NBATCH][32][NC];

/* ================= helpers ================= */
__device__ __forceinline__ uint32_t smem_u32(const void* p) {
    uint32_t a;
    asm("{ .reg .u64 t; cvta.to.shared.u64 t, %1; cvt.u32.u64 %0, t; }" : "=r"(a) : "l"(p));
    return a;
}
__device__ __forceinline__ float ex2f(float x) {
    float y; asm("ex2.approx.ftz.f32 %0, %1;" : "=f"(y) : "f"(x)); return y;
}
__device__ __forceinline__ void cp16(uint32_t dst, const void* src) {
    asm volatile("cp.async.cg.shared.global [%0], [%1], 16;" :: "r"(dst), "l"(src));
}
#define CP_COMMIT() asm volatile("cp.async.commit_group;" ::: "memory")
#define CP_WAIT0()  asm volatile("cp.async.wait_group 0;" ::: "memory")
#define BARH(id)    asm volatile("bar.sync %0, %1;" :: "r"(id), "r"(256) : "memory")

__device__ __forceinline__ void ldsm4(uint32_t (&r)[4], uint32_t addr) {
    asm volatile("ldmatrix.sync.aligned.m8n8.x4.shared.b16 {%0,%1,%2,%3}, [%4];"
                 : "=r"(r[0]), "=r"(r[1]), "=r"(r[2]), "=r"(r[3]) : "r"(addr));
}
__device__ __forceinline__ void mma_h(float (&d)[4], const uint32_t* a, const uint32_t* b) {
    asm volatile("mma.sync.aligned.m16n8k16.row.col.f32.f16.f16.f32 "
                 "{%0,%1,%2,%3}, {%4,%5,%6,%7}, {%8,%9}, {%0,%1,%2,%3};"
                 : "+f"(d[0]), "+f"(d[1]), "+f"(d[2]), "+f"(d[3])
                 : "r"(a[0]), "r"(a[1]), "r"(a[2]), "r"(a[3]), "r"(b[0]), "r"(b[1]));
}
__device__ __forceinline__ uint32_t pkh(__half a, __half b) {
    return (uint32_t)__half_as_ushort(a) | ((uint32_t)__half_as_ushort(b) << 16);
}
__device__ __forceinline__ unsigned fkey(float x) {
    unsigned u = __float_as_uint(x);
    return (u & 0x80000000u) ? ~u : (u | 0x80000000u);
}
__device__ __forceinline__ float funkey(unsigned k) {
    unsigned u = (k & 0x80000000u) ? (k & 0x7FFFFFFFu) : ~k;
    return __uint_as_float(u);
}

/* ================= Kernel 0: tgt -> fp16 hi + positive-logit dot =============
   one warp per row: converts tgt row and computes exact fp32 src.tgt dot.    */
__global__ __launch_bounds__(256)
void cvt_pos(const float* __restrict__ src, const float* __restrict__ tgt)
{
    const int w = threadIdx.x >> 5, lane = threadIdx.x & 31;
    const int row = blockIdx.x * 8 + w;
    const float4* s4 = (const float4*)(src + (size_t)row * DIM);
    const float4* t4 = (const float4*)(tgt + (size_t)row * DIM);
    float p = 0.f;
#pragma unroll
    for (int j = 0; j < 2; j++) {
        float4 a = s4[lane * 2 + j], v = t4[lane * 2 + j];
        p += a.x * v.x + a.y * v.y + a.z * v.z + a.w * v.w;
        ((uint2*)g_Bh)[row * 64 + lane * 2 + j] = make_uint2(
            pkh(__float2half_rn(v.x), __float2half_rn(v.y)),
            pkh(__float2half_rn(v.z), __float2half_rn(v.w)));
    }
#pragma unroll
    for (int d = 16; d > 0; d >>= 1) p += __shfl_xor_sync(0xFFFFFFFFu, p, d);
    if (lane == 0) g_pos[row] = p * INV_T;
}

/* ================= Kernel 1: fp16 mma GEMM + fused masked softmax =============
   grid (32 M-tiles, 4 batches), 512 threads = TWO independent 8-warp halves.
   Half h owns N-cols [h*2048, (h+1)*2048): own B stages (4 x 16KB ring), own
   cp.async groups, own named barrier -> halves drift, so one half's epilogue
   (MUFU/ALU) overlaps the other half's HMMA on the same SMSPs.
   Per half: 8 warps as 2(M) x 4(N), warp tile 64x32, 64 iterations
   (ct = 128-col tile, kc = 64-k chunk). A shared, resident.                  */
__global__ __launch_bounds__(512, 1)
void nce_gemm_mma(const float* __restrict__ src, const int* __restrict__ cls)
{
    extern __shared__ __align__(1024) char smem[];
    const uint32_t sb = smem_u32(smem);
    const int tid = threadIdx.x, lane = tid & 31, w = tid >> 5;
    const int h = w >> 3, w7 = w & 7;
    const int wm = w7 >> 2, wn = w7 & 3;
    const int tid2 = tid & 255;
    const int b = blockIdx.y, mtB = blockIdx.x;
    const int R0 = b * NP + mtB * 128;
    const float NEGINF = __int_as_float(0xff800000);
    const float POSINF = __int_as_float(0x7f800000);
    int* scls = (int*)(smem + SM_CLS);

    __shared__ int      sh_h[NC];
    __shared__ unsigned sh_mk[NC];
    if (tid < NC) { sh_h[tid] = 0; sh_mk[tid] = 0xFF800000u; /* fkey(+inf) */ }

    /* ---- B stage loader (per half, 256 threads): tile i = (ct=i>>2, kc=i&3)
       stage = 128 rows x 128B, swizzle chunk^(row&7), ring slot = i&3.       */
    auto loadB = [&](int i) {
        const int ct = i >> 2, kc = i & 3, slot = i & 3;
        const uint32_t* __restrict__ gh =
            g_Bh + (size_t)(b * NP + h * 2048 + ct * 128) * 128 + kc * 32;
        const uint32_t dbase = sb + SM_B + (uint32_t)h * 65536u + (uint32_t)slot * 16384u;
#pragma unroll
        for (int q = 0; q < 4; q++) {
            int idx = tid2 + q * 256;                /* 0..1023 */
            int n = idx >> 3, c = idx & 7;
            uint32_t dst = dbase + (uint32_t)n * 128u + (uint32_t)((c ^ (n & 7)) << 4);
            cp16(dst, gh + (size_t)n * 128 + c * 4);
        }
    };
    loadB(0); CP_COMMIT();
    loadB(1); CP_COMMIT();

    /* ---- A prologue: fp32 rows -> fp16, swizzled STS (row*512 + (c^row&7)*16) */
    {
        const float4* Ag = (const float4*)(src + (size_t)R0 * DIM);
#pragma unroll
        for (int q = 0; q < 8; q++) {
            int line = tid + q * 512;               /* 0..4095 */
            int row = line >> 5, c = line & 31;
            float4 v0 = Ag[row * 64 + c * 2];
            float4 v1 = Ag[row * 64 + c * 2 + 1];
            uint4 hh4 = make_uint4(pkh(__float2half_rn(v0.x), __float2half_rn(v0.y)),
                                   pkh(__float2half_rn(v0.z), __float2half_rn(v0.w)),
                                   pkh(__float2half_rn(v1.x), __float2half_rn(v1.y)),
                                   pkh(__float2half_rn(v1.z), __float2half_rn(v1.w)));
            *(uint4*)(smem + SM_A + row * 512 + ((c ^ (row & 7)) << 4)) = hh4;
        }
    }

    /* ---- class table ---- */
#pragma unroll
    for (int q = 0; q < 2; q++)
        ((int4*)scls)[tid + q * 512] = ((const int4*)(cls + b * NP))[tid + q * 512];

    /* ---- per-lane constants ---- */
    const int la7 = lane & 7;
    const int aRowBase = wm * 64 + ((lane >> 3) & 1) * 8 + la7;    /* + mt*16 */
    const uint32_t aOff = sb + SM_A + (uint32_t)aRowBase * 512u;
    const int a7s = aRowBase & 7;
    const int aKg = lane >> 4;                                     /* k8 group */
    const int nB = wn * 32 + ((lane >> 4) & 1) * 8 + la7;          /* + p*16 */
    const uint32_t bOff = (uint32_t)nB * 128u;
    const int b7s = nB & 7;
    const int bKg = (lane >> 3) & 1;
    const uint32_t Bhalf = sb + SM_B + (uint32_t)h * 65536u;

    float m_[8], s_[8], mn_[8];
#pragma unroll
    for (int j = 0; j < 8; j++) { m_[j] = NEGINF; s_[j] = 0.f; mn_[j] = POSINF; }

    float acc[4][4][4];

    /* ---- epilogue: masked online update over this half's 128-col tile ---- */
    auto epilogue = [&](int ct) {
        const int cb = h * 2048 + ct * 128 + wn * 32 + (lane & 3) * 2;
        int ccls[8];
#pragma unroll
        for (int nt = 0; nt < 4; nt++) {
            ccls[nt * 2]     = scls[cb + nt * 8];
            ccls[nt * 2 + 1] = scls[cb + nt * 8 + 1];
        }
#pragma unroll
        for (int j = 0; j < 8; j++) {
            const int mt = j >> 1, hh = j & 1;
            const int rcl = scls[mtB * 128 + wm * 64 + mt * 16 + hh * 8 + (lane >> 2)];
            float tmax = NEGINF;
#pragma unroll
            for (int nt = 0; nt < 4; nt++) {
                float l0 = acc[mt][nt][hh * 2], l1 = acc[mt][nt][hh * 2 + 1];
                if (ccls[nt * 2] != rcl)     { mn_[j] = fminf(mn_[j], l0); tmax = fmaxf(tmax, l0); }
                if (ccls[nt * 2 + 1] != rcl) { mn_[j] = fminf(mn_[j], l1); tmax = fmaxf(tmax, l1); }
            }
            if (tmax != NEGINF) {
                float nm = fmaxf(m_[j], tmax * CQ);
                float a0 = 0.f, a1 = 0.f;
#pragma unroll
                for (int nt = 0; nt < 4; nt++) {
                    float l0 = acc[mt][nt][hh * 2], l1 = acc[mt][nt][hh * 2 + 1];
                    a0 += ex2f((ccls[nt * 2] != rcl)     ? l0 * CQ - nm : NEGINF);
                    a1 += ex2f((ccls[nt * 2 + 1] != rcl) ? l1 * CQ - nm : NEGINF);
                }
                s_[j] = s_[j] * ex2f(m_[j] - nm) + a0 + a1;
                m_[j] = nm;
            }
        }
    };

    /* initial: A + cls + stages 0,1 of both halves complete and visible */
    CP_WAIT0();
    __syncthreads();

#pragma unroll 1
    for (int i = 0; i < 64; i++) {
        if (i & 1) {                 /* per-half barrier at odd iterations */
            CP_WAIT0();
            BARH(h + 1);
        }
        if (i < 62) { loadB(i + 2); CP_COMMIT(); }

        const int kc = i & 3, ct = i >> 2;
        const uint32_t Bst = Bhalf + (uint32_t)(i & 3) * 16384u;
        if (kc == 0) {
#pragma unroll
            for (int mt = 0; mt < 4; mt++)
#pragma unroll
                for (int nt = 0; nt < 4; nt++)
#pragma unroll
                    for (int j = 0; j < 4; j++) acc[mt][nt][j] = 0.f;
        }

#pragma unroll
        for (int ks = 0; ks < 4; ks++) {
            uint32_t bh[2][4];
            const uint32_t cb = (uint32_t)((ks * 2 + bKg) ^ b7s) << 4;
#pragma unroll
            for (int p = 0; p < 2; p++)
                ldsm4(bh[p], Bst + bOff + (uint32_t)p * 2048u + cb);
            const uint32_t ach = (uint32_t)(kc * 8 + ks * 2 + aKg);
#pragma unroll
            for (int mt = 0; mt < 4; mt++) {
                uint32_t ah[4];
                ldsm4(ah, aOff + (uint32_t)mt * 8192u + ((ach ^ (uint32_t)a7s) << 4));
#pragma unroll
                for (int p = 0; p < 2; p++)
#pragma unroll
                    for (int hh = 0; hh < 2; hh++)
                        mma_h(acc[mt][p * 2 + hh], ah, &bh[p][hh * 2]);
            }
        }

        if (kc == 3) epilogue(ct);
    }

    /* ---- merge across the 4 lanes sharing each row (lane bits 0,1) ---- */
#pragma unroll
    for (int j = 0; j < 8; j++) {
#pragma unroll
        for (int d = 1; d <= 2; d <<= 1) {
            float om = __shfl_xor_sync(0xFFFFFFFFu, m_[j], d);
            float os = __shfl_xor_sync(0xFFFFFFFFu, s_[j], d);
            float on = __shfl_xor_sync(0xFFFFFFFFu, mn_[j], d);
            float nm = fmaxf(m_[j], om);
            float t0 = (m_[j] == NEGINF) ? 0.f : s_[j] * ex2f(m_[j] - nm);
            float t1 = (om == NEGINF) ? 0.f : os * ex2f(om - nm);
            s_[j] = t0 + t1; m_[j] = nm; mn_[j] = fminf(mn_[j], on);
        }
    }

    /* ---- cross-warp merge: 8 partials per row (4 wn x 2 halves) ---- */
    __syncthreads();
    float* mgM = (float*)(smem + SM_B);        /* [8][128] */
    float* mgS = mgM + 1024;
    float* mgN = mgS + 1024;
    if ((lane & 3) == 0) {
        const int slot = h * 4 + wn;
#pragma unroll
        for (int j = 0; j < 8; j++) {
            int row = wm * 64 + (j >> 1) * 16 + (j & 1) * 8 + (lane >> 2);
            mgM[slot * 128 + row] = m_[j];
            mgS[slot * 128 + row] = s_[j];
            mgN[slot * 128 + row] = mn_[j];
        }
    }
    __syncthreads();
    if (tid < 128) {
        float M = NEGINF, S = 0.f, MN = POSINF;
#pragma unroll
        for (int t = 0; t < 8; t++) M = fmaxf(M, mgM[t * 128 + tid]);
        if (M != NEGINF) {
#pragma unroll
            for (int t = 0; t < 8; t++) {
                float mt_ = mgM[t * 128 + tid];
                if (mt_ != NEGINF) S += mgS[t * 128 + tid] * ex2f(mt_ - M);
            }
        }
#pragma unroll
        for (int t = 0; t < 8; t++) MN = fminf(MN, mgN[t * 128 + tid]);
        g_m[R0 + tid] = M;
        g_s[R0 + tid] = S;
        /* per-chunk class histogram + class-min */
        int c = scls[mtB * 128 + tid];
        atomicAdd(&sh_h[c], 1);
        atomicMin(&sh_mk[c], fkey(MN));
    }
    __syncthreads();
    if (tid < NC) {
        g_hist [b][mtB][tid] = sh_h[tid];
        g_chmin[b][mtB][tid] = sh_mk[tid];
    }
}

/* ================= Kernel 2: final 3-way LSE + stable class-sorted scatter === */
__global__ void nce_final(const int* __restrict__ cls, float* __restrict__ out)
{
    const int ch = blockIdx.x, b = blockIdx.y, tid = threadIdx.x;
    const int lane = tid & 31, w = tid >> 5;
    const int row = b * NP + ch * 128 + tid;
    const float NEGINF = __int_as_float(0xff800000);

    __shared__ int      hist_s[32][NC];
    __shared__ unsigned chm_s [32][NC];
    __shared__ int      pref_s[NC];
    __shared__ int      cnt_s [NC];
    __shared__ float    small_s[NC];
    __shared__ int      wcnt[4][NC];

    for (int i = tid; i < 32 * NC; i += 128) {
        ((int*)hist_s)[i]     = ((const int*)g_hist [b])[i];
        ((unsigned*)chm_s)[i] = ((const unsigned*)g_chmin[b])[i];
    }
    __syncthreads();
    if (tid < NC) {
        int run = 0, mypref = 0;
        unsigned mn = 0xFF800000u;
        for (int h2 = 0; h2 < 32; h2++) {
            if (h2 == ch) mypref = run;
            run += hist_s[h2][tid];
            mn = min(mn, chm_s[h2][tid]);
        }
        pref_s[tid] = mypref;
        cnt_s[tid] = run;
        small_s[tid] = fminf(funkey(mn), -10.0f) * INV_T;
    }

    const int c = cls[row];
    unsigned match = __match_any_sync(0xFFFFFFFFu, c);
    int lr = __popc(match & ((1u << lane) - 1u));
#pragma unroll
    for (int c2 = 0; c2 < NC; c2++) {
        unsigned bal = __ballot_sync(0xFFFFFFFFu, c == c2);
        if (lane == c2) wcnt[w][c2] = __popc(bal);
    }
    __syncthreads();
    for (int w2 = 0; w2 < w; w2++) lr += wcnt[w2][c];
    int classpref = 0;
    for (int c2 = 0; c2 < c; c2++) classpref += cnt_s[c2];
    const int opos = b * NP + classpref + pref_s[c] + lr;

    const float pos_n = g_pos[row];
    const float M = g_m[row], S = g_s[row];
    const float lneg = (S > 0.f) ? (M * LN2F + logf(S)) : NEGINF;

    const int   npad = cnt_s[c] - 1;
    const float pad  = (npad > 0) ? (logf((float)npad) + small_s[c]) : NEGINF;

    const float Mx  = fmaxf(pos_n, fmaxf(lneg, pad));
    const float sum = expf(pos_n - Mx) + expf(lneg - Mx) + expf(pad - Mx);
    out[opos] = Mx + logf(sum) - pos_n;
}

/* ============================================================================ */
extern "C" void kernel_launch(void* const* d_in, const int* in_sizes, int n_in,
                              void* d_out, int out_size)
{
    const float* src = (const float*)d_in[0];
    const float* tgt = (const float*)d_in[1];
    const int*   cls = (const int*)d_in[2];
    float*       out = (float*)d_out;

    cudaFuncSetAttribute(nce_gemm_mma, cudaFuncAttributeMaxDynamicSharedMemorySize, SMEM_BYTES);

    cvt_pos<<<NROWS / 8, 256>>>(src, tgt);
    nce_gemm_mma<<<dim3(32, NBATCH), 512, SMEM_BYTES>>>(src, cls);
    nce_final<<<dim3(32, NBATCH), 128>>>(cls, out);
}